// round 1
// baseline (speedup 1.0000x reference)
#include <cuda_runtime.h>
#include <math.h>

#define BB   4
#define NN   4096
#define CC   64      // CIN == COUT
#define KNN  16
#define NH   4
#define DH   16

// ---------------- scratch (device globals: allocation-free) ----------------
__device__ int   g_idx[BB * NN * KNN];
__device__ float g_WkT[CC * CC];
__device__ float g_WvT[CC * CC];
__device__ float g_WpT[CC * CC];

// ---------------- prep: transpose weights for coalesced float4 loads -------
__global__ void prep_kernel(const float* __restrict__ Wk,
                            const float* __restrict__ Wv,
                            const float* __restrict__ Wp2) {
    int t = blockIdx.x * blockDim.x + threadIdx.x;   // t = r*64 + c
    if (t < CC * CC) {
        int r = t >> 6, c = t & 63;
        g_WkT[c * CC + r] = Wk[t];
        g_WvT[c * CC + r] = Wv[t];
        g_WpT[c * CC + r] = Wp2[t];
    }
}

// ---------------- kNN: thread-per-query, tiled candidates in smem ----------
// neg_sqdist = 2*dot(p_q,p_m) - |p_q|^2 - |p_m|^2 (matches reference formula).
// Sequential candidate scan + strict '>' insert reproduces jax top_k's
// lowest-index tie-break for the SET of neighbors (order irrelevant: softmax
// over K commutes).
__global__ __launch_bounds__(128) void knn_kernel(const float* __restrict__ pos) {
    __shared__ float4 cand[128];
    const int b  = blockIdx.x >> 5;          // 32 query-tiles per batch
    const int qt = blockIdx.x & 31;
    const int q  = qt * 128 + threadIdx.x;
    const float* pb = pos + (size_t)b * NN * 3;

    const float qx = pb[q * 3 + 0], qy = pb[q * 3 + 1], qz = pb[q * 3 + 2];
    float qxx = qx * qx; qxx = fmaf(qy, qy, qxx); qxx = fmaf(qz, qz, qxx);

    float bvv[KNN]; int bii[KNN];
#pragma unroll
    for (int i = 0; i < KNN; i++) { bvv[i] = -3.402823466e+38f; bii[i] = 0x7fffffff - i; }
    float wv = -3.402823466e+38f; int ws = 0; int widx = 0x7fffffff;

    for (int tile = 0; tile < NN / 128; tile++) {
        int m = tile * 128 + threadIdx.x;
        float cx = pb[m * 3 + 0], cy = pb[m * 3 + 1], cz = pb[m * 3 + 2];
        float cxx = cx * cx; cxx = fmaf(cy, cy, cxx); cxx = fmaf(cz, cz, cxx);
        cand[threadIdx.x] = make_float4(cx, cy, cz, cxx);
        __syncthreads();
#pragma unroll 4
        for (int j = 0; j < 128; j++) {
            float4 c4 = cand[j];
            float inner = qx * c4.x;
            inner = fmaf(qy, c4.y, inner);
            inner = fmaf(qz, c4.z, inner);
            float d = 2.0f * inner - qxx - c4.w;
            if (d > wv) {                       // rare after warm-up
                bvv[ws] = d; bii[ws] = tile * 128 + j;
                wv = bvv[0]; ws = 0; widx = bii[0];
#pragma unroll
                for (int i = 1; i < KNN; i++) {
                    bool worse = (bvv[i] < wv) || (bvv[i] == wv && bii[i] > widx);
                    if (worse) { wv = bvv[i]; ws = i; widx = bii[i]; }
                }
            }
        }
        __syncthreads();
    }
    int* op = g_idx + ((size_t)b * NN + q) * KNN;
#pragma unroll
    for (int i = 0; i < KNN; i++) op[i] = bii[i];
}

// ---------------- fused attention: one block per query point ----------------
// 256 threads: t = k*16 + jg; thread owns (neighbor k, channels jc..jc+3).
__global__ __launch_bounds__(256) void fused_kernel(
    const float* __restrict__ x,   const float* __restrict__ pos,
    const float* __restrict__ Wq,  const float* __restrict__ bq,
    const float* __restrict__ bk,  const float* __restrict__ bv,
    const float* __restrict__ Wp1, const float* __restrict__ bp1,
    const float* __restrict__ bp2,
    const float* __restrict__ Wfc, const float* __restrict__ bfc,
    float* __restrict__ out)
{
    __shared__ float xnb[KNN][68];   // gathered neighbor features (padded)
    __shared__ float hid[KNN][68];   // relu hidden of pos MLP; reused later
    __shared__ float xq[CC];
    __shared__ float qs[CC];
    __shared__ float pd[KNN][4];
    __shared__ int   idxs[KNN];
    __shared__ float ss[KNN * NH];
    __shared__ float attn[KNN * NH];
    __shared__ float aggs[CC];

    const int p  = blockIdx.x;
    const int b  = p >> 12;          // N = 4096
    const int n  = p & 4095;
    const int t  = threadIdx.x;
    const int k  = t >> 4;
    const int jg = t & 15;
    const int jc = jg * 4;

    // --- stage 1: load x row + neighbor indices ---
    if (t < CC) xq[t] = x[(size_t)p * CC + t];
    if (t < KNN) idxs[t] = g_idx[(size_t)p * KNN + t];
    __syncthreads();

    // --- stage 2: gather neighbor rows (float4 each) + pos diffs ---
    {
        int m = idxs[k];
        const float* xr = x + ((size_t)b * NN + m) * CC;
        float4 v4 = *(const float4*)(xr + jc);
        *(float4*)&xnb[k][jc] = v4;
    }
    if (t < KNN) {
        int m = idxs[t];
        const float* pq = pos + ((size_t)b * NN + n) * 3;
        const float* pm = pos + ((size_t)b * NN + m) * 3;
        pd[t][0] = pq[0] - pm[0];
        pd[t][1] = pq[1] - pm[1];
        pd[t][2] = pq[2] - pm[2];
    }
    __syncthreads();

    // --- stage 3: hidden = relu(pos_diff @ Wp1^T + bp1) ---
    {
        float dx = pd[k][0], dy = pd[k][1], dz = pd[k][2];
#pragma unroll
        for (int i = 0; i < 4; i++) {
            int j = jc + i;
            float h = bp1[j];
            h = fmaf(Wp1[j * 3 + 0], dx, h);
            h = fmaf(Wp1[j * 3 + 1], dy, h);
            h = fmaf(Wp1[j * 3 + 2], dz, h);
            hid[k][j] = fmaxf(h, 0.0f);
        }
    }
    // --- q = x @ Wq^T + bq (threads 0..63, row-major float4) ---
    if (t < CC) {
        float acc = bq[t];
        const float4* wr = (const float4*)(Wq + t * CC);
#pragma unroll
        for (int c4 = 0; c4 < 16; c4++) {
            float4 w = wr[c4];
            acc = fmaf(w.x, xq[c4 * 4 + 0], acc);
            acc = fmaf(w.y, xq[c4 * 4 + 1], acc);
            acc = fmaf(w.z, xq[c4 * 4 + 2], acc);
            acc = fmaf(w.w, xq[c4 * 4 + 3], acc);
        }
        qs[t] = acc;
    }
    __syncthreads();

    // --- stage 4: main accumulation: kf, v, pe for (k, jc..jc+3) ---
    float kf[4], vv[4], pe[4];
#pragma unroll
    for (int i = 0; i < 4; i++) {
        kf[i] = bk[jc + i]; vv[i] = bv[jc + i]; pe[i] = bp2[jc + i];
    }
#pragma unroll 4
    for (int c = 0; c < CC; c++) {
        float xv = xnb[k][c];     // broadcast LDS
        float hv = hid[k][c];     // broadcast LDS
        float4 wk4 = *(const float4*)(g_WkT + c * CC + jc);
        float4 wv4 = *(const float4*)(g_WvT + c * CC + jc);
        float4 wp4 = *(const float4*)(g_WpT + c * CC + jc);
        kf[0] = fmaf(xv, wk4.x, kf[0]); kf[1] = fmaf(xv, wk4.y, kf[1]);
        kf[2] = fmaf(xv, wk4.z, kf[2]); kf[3] = fmaf(xv, wk4.w, kf[3]);
        vv[0] = fmaf(xv, wv4.x, vv[0]); vv[1] = fmaf(xv, wv4.y, vv[1]);
        vv[2] = fmaf(xv, wv4.z, vv[2]); vv[3] = fmaf(xv, wv4.w, vv[3]);
        pe[0] = fmaf(hv, wp4.x, pe[0]); pe[1] = fmaf(hv, wp4.y, pe[1]);
        pe[2] = fmaf(hv, wp4.z, pe[2]); pe[3] = fmaf(hv, wp4.w, pe[3]);
    }

    // --- stage 5: logits s[k][h] = mean_d(q - kf + pe) ---
    float part = 0.0f;
#pragma unroll
    for (int i = 0; i < 4; i++) part += qs[jc + i] - kf[i] + pe[i];
    part += __shfl_xor_sync(0xffffffffu, part, 1);
    part += __shfl_xor_sync(0xffffffffu, part, 2);
    const int h = jg >> 2;
    if ((jg & 3) == 0) ss[k * NH + h] = part * (1.0f / 16.0f);
    __syncthreads();

    // --- stage 6: softmax over K (4 threads, one per head) ---
    if (t < NH) {
        float mx = -3.402823466e+38f;
        for (int kk = 0; kk < KNN; kk++) mx = fmaxf(mx, ss[kk * NH + t]);
        float e[KNN]; float sum = 0.0f;
#pragma unroll
        for (int kk = 0; kk < KNN; kk++) { e[kk] = expf(ss[kk * NH + t] - mx); sum += e[kk]; }
        float inv = 1.0f / sum;
#pragma unroll
        for (int kk = 0; kk < KNN; kk++) attn[kk * NH + t] = e[kk] * inv;
    }
    __syncthreads();

    // --- stage 7: aggregate: agg[j] = sum_k attn[k][h]*(v+pe) (reuse hid) ---
    {
        float w = attn[k * NH + h];
#pragma unroll
        for (int i = 0; i < 4; i++) hid[k][jc + i] = w * (vv[i] + pe[i]);
    }
    __syncthreads();
    if (t < CC) {
        float acc = 0.0f;
#pragma unroll
        for (int kk = 0; kk < KNN; kk++) acc += hid[kk][t];
        aggs[t] = acc;
    }
    __syncthreads();

    // --- stage 8: fc + residual ---
    if (t < CC) {
        float acc = bfc[t];
        const float4* wr = (const float4*)(Wfc + t * CC);
#pragma unroll
        for (int c4 = 0; c4 < 16; c4++) {
            float4 w = wr[c4];
            acc = fmaf(w.x, aggs[c4 * 4 + 0], acc);
            acc = fmaf(w.y, aggs[c4 * 4 + 1], acc);
            acc = fmaf(w.z, aggs[c4 * 4 + 2], acc);
            acc = fmaf(w.w, aggs[c4 * 4 + 3], acc);
        }
        out[(size_t)p * CC + t] = xq[t] + acc;
    }
}

// ---------------- launch -----------------------------------------------------
extern "C" void kernel_launch(void* const* d_in, const int* in_sizes, int n_in,
                              void* d_out, int out_size) {
    const float* x   = (const float*)d_in[0];
    const float* pos = (const float*)d_in[1];
    const float* Wq  = (const float*)d_in[2];
    const float* bq  = (const float*)d_in[3];
    const float* Wk  = (const float*)d_in[4];
    const float* bk  = (const float*)d_in[5];
    const float* Wv  = (const float*)d_in[6];
    const float* bv  = (const float*)d_in[7];
    const float* Wp1 = (const float*)d_in[8];
    const float* bp1 = (const float*)d_in[9];
    const float* Wp2 = (const float*)d_in[10];
    const float* bp2 = (const float*)d_in[11];
    const float* Wfc = (const float*)d_in[12];
    const float* bfc = (const float*)d_in[13];
    float* out = (float*)d_out;

    prep_kernel<<<16, 256>>>(Wk, Wv, Wp2);
    knn_kernel<<<(BB * NN) / 128, 128>>>(pos);
    fused_kernel<<<BB * NN, 256>>>(x, pos, Wq, bq, bk, bv,
                                   Wp1, bp1, bp2, Wfc, bfc, out);
}

// round 3
// speedup vs baseline: 1.2359x; 1.2359x over previous
#include <cuda_runtime.h>
#include <math.h>

#define BB   4
#define NN   4096
#define CC   64
#define KNN  16
#define NH   4
#define SEG  8
#define SEGLEN (NN / SEG)   // 512

// ---------------- device scratch (allocation-free) ----------------
__device__ int   g_idx [BB * NN * KNN];
__device__ float g_cval[BB * NN * SEG * KNN];
__device__ int   g_cidx[BB * NN * SEG * KNN];
__device__ float g_WvT[CC * CC];
__device__ float g_WpT[CC * CC];
__device__ float g_Wkm[CC * NH];
__device__ float g_Wqm[CC * NH];
__device__ float g_bkm[NH];
__device__ float g_bqm[NH];

// ---------------- packed f32x2 helpers ----------------
__device__ __forceinline__ unsigned long long pack2(float lo, float hi) {
    unsigned long long r;
    asm("mov.b64 %0, {%1, %2};" : "=l"(r) : "f"(lo), "f"(hi));
    return r;
}
__device__ __forceinline__ float2 unpack2(unsigned long long v) {
    float2 f;
    asm("mov.b64 {%0, %1}, %2;" : "=f"(f.x), "=f"(f.y) : "l"(v));
    return f;
}
#define FMA2(acc, a, b) asm("fma.rn.f32x2 %0, %1, %2, %0;" : "+l"(acc) : "l"(a), "l"(b))

// ---------------- prep: transposes + head-mean projections ----------------
__global__ void prep_kernel(const float* __restrict__ Wq, const float* __restrict__ Wk,
                            const float* __restrict__ Wv, const float* __restrict__ Wp2,
                            const float* __restrict__ bq, const float* __restrict__ bk) {
    int t = blockIdx.x * 256 + threadIdx.x;
    if (t < CC * CC) {
        int r = t >> 6, c = t & 63;
        g_WvT[c * CC + r] = Wv[t];
        g_WpT[c * CC + r] = Wp2[t];
    }
    if (blockIdx.x == 0) {
        int tt = threadIdx.x;            // 256 threads: c = tt>>2, h = tt&3
        int c = tt >> 2, hh = tt & 3;
        float sk = 0.f, sq = 0.f;
#pragma unroll
        for (int d = 0; d < 16; d++) {
            sk += Wk[(hh * 16 + d) * CC + c];
            sq += Wq[(hh * 16 + d) * CC + c];
        }
        g_Wkm[c * NH + hh] = sk * (1.f / 16.f);
        g_Wqm[c * NH + hh] = sq * (1.f / 16.f);
        if (tt < NH) {
            float s1 = 0.f, s2 = 0.f;
            for (int d = 0; d < 16; d++) { s1 += bk[tt * 16 + d]; s2 += bq[tt * 16 + d]; }
            g_bkm[tt] = s1 * (1.f / 16.f);
            g_bqm[tt] = s2 * (1.f / 16.f);
        }
    }
}

// ---------------- kNN part: per-segment top-16 ----------------
__global__ __launch_bounds__(128) void knn_part(const float* __restrict__ pos) {
    __shared__ float4 cand[128];
    const int b   = blockIdx.x >> 8;          // 32 qtiles * 8 segs per batch
    const int rem = blockIdx.x & 255;
    const int qt  = rem >> 3;
    const int seg = rem & 7;
    const int q   = qt * 128 + threadIdx.x;
    const float* pb = pos + (size_t)b * NN * 3;

    const float qx = pb[q * 3 + 0], qy = pb[q * 3 + 1], qz = pb[q * 3 + 2];
    float qxx = qx * qx; qxx = fmaf(qy, qy, qxx); qxx = fmaf(qz, qz, qxx);

    float bvv[KNN]; int bii[KNN];
#pragma unroll
    for (int i = 0; i < KNN; i++) { bvv[i] = -3.402823466e+38f; bii[i] = 0x7fffffff - i; }
    float wv = -3.402823466e+38f; int ws = 0; int widx = 0x7fffffff;

    for (int tile = 0; tile < SEGLEN / 128; tile++) {
        int m = seg * SEGLEN + tile * 128 + threadIdx.x;
        float cx = pb[m * 3 + 0], cy = pb[m * 3 + 1], cz = pb[m * 3 + 2];
        float cxx = cx * cx; cxx = fmaf(cy, cy, cxx); cxx = fmaf(cz, cz, cxx);
        cand[threadIdx.x] = make_float4(cx, cy, cz, cxx);
        __syncthreads();
#pragma unroll 4
        for (int j = 0; j < 128; j++) {
            float4 c4 = cand[j];
            float inner = qx * c4.x;
            inner = fmaf(qy, c4.y, inner);
            inner = fmaf(qz, c4.z, inner);
            float d = 2.0f * inner - qxx - c4.w;
            int   mi = seg * SEGLEN + tile * 128 + j;
            if ((d > wv) || (d == wv && mi < widx)) {
                bvv[ws] = d; bii[ws] = mi;
                wv = bvv[0]; ws = 0; widx = bii[0];
#pragma unroll
                for (int i = 1; i < KNN; i++) {
                    bool worse = (bvv[i] < wv) || (bvv[i] == wv && bii[i] > widx);
                    if (worse) { wv = bvv[i]; ws = i; widx = bii[i]; }
                }
            }
        }
        __syncthreads();
    }
    size_t base = (((size_t)b * NN + q) * SEG + seg) * KNN;
#pragma unroll
    for (int i = 0; i < KNN; i++) { g_cval[base + i] = bvv[i]; g_cidx[base + i] = bii[i]; }
}

// ---------------- kNN merge: 8x16 -> 16 ----------------
__global__ __launch_bounds__(128) void knn_merge() {
    const int q = blockIdx.x * 128 + threadIdx.x;    // global point id
    size_t base = (size_t)q * (SEG * KNN);

    float bvv[KNN]; int bii[KNN];
#pragma unroll
    for (int i = 0; i < KNN; i++) { bvv[i] = -3.402823466e+38f; bii[i] = 0x7fffffff - i; }
    float wv = -3.402823466e+38f; int ws = 0; int widx = 0x7fffffff;

    for (int i = 0; i < SEG * KNN; i++) {
        float d  = g_cval[base + i];
        int   mi = g_cidx[base + i];
        if ((d > wv) || (d == wv && mi < widx)) {
            bvv[ws] = d; bii[ws] = mi;
            wv = bvv[0]; ws = 0; widx = bii[0];
#pragma unroll
            for (int k = 1; k < KNN; k++) {
                bool worse = (bvv[k] < wv) || (bvv[k] == wv && bii[k] > widx);
                if (worse) { wv = bvv[k]; ws = k; widx = bii[k]; }
            }
        }
    }
    int* op = g_idx + (size_t)q * KNN;
#pragma unroll
    for (int i = 0; i < KNN; i++) op[i] = bii[i];
}

// ---------------- fused: 8 points / block, weights in smem, f32x2 ----------
// smem float offsets
#define OFF_WVT  0
#define OFF_WPT  4096
#define OFF_WKM  8192
#define OFF_WQM  8448
#define OFF_XQ   8704
#define OFF_PD   8960
#define OFF_IDX  9216
#define OFF_KLOG 9280
#define OFF_QM   9536
#define OFF_LOG  9552
#define OFF_ATTN 9808
#define OFF_XH   10240           // float2[4][16][64] = 8192 floats
#define SMEM_FLOATS 18432        // 73728 bytes

__global__ __launch_bounds__(256, 3) void fused_kernel(
    const float* __restrict__ x,   const float* __restrict__ pos,
    const float* __restrict__ bv,  const float* __restrict__ Wp1,
    const float* __restrict__ bp1, const float* __restrict__ bp2,
    const float* __restrict__ Wfc, const float* __restrict__ bfc,
    float* __restrict__ out)
{
    extern __shared__ float SW[];
    const int t  = threadIdx.x;
    const int pt = t >> 6;           // 4 points at a time
    const int tp = t & 63;
    const int k2 = tp >> 3;          // handles neighbors k2 and k2+8
    const int jg = tp & 7;
    const int jc = jg * 8;
    const int h0 = jg >> 1;          // head of channels jc..jc+7

    // stage weights once per block
    for (int i = t; i < CC * CC; i += 256) {
        SW[OFF_WVT + i] = g_WvT[i];
        SW[OFF_WPT + i] = g_WpT[i];
    }
    if (t < CC * NH) { SW[OFF_WKM + t] = g_Wkm[t]; SW[OFF_WQM + t] = g_Wqm[t]; }
    __syncthreads();

    for (int r = 0; r < 2; r++) {
        const int p = blockIdx.x * 8 + r * 4 + pt;
        const int b = p >> 12;
        const int n = p & 4095;

        // --- S0: xq, idx, pos diffs ---
        SW[OFF_XQ + pt * 64 + tp] = x[(size_t)p * CC + tp];
        if (tp < KNN) {
            int m = g_idx[(size_t)p * KNN + tp];
            ((int*)(SW + OFF_IDX))[pt * 16 + tp] = m;
            const float* pq = pos + ((size_t)b * NN + n) * 3;
            const float* pm = pos + ((size_t)b * NN + m) * 3;
            float* pdp = SW + OFF_PD + (pt * 16 + tp) * 4;
            pdp[0] = pq[0] - pm[0];
            pdp[1] = pq[1] - pm[1];
            pdp[2] = pq[2] - pm[2];
        }
        __syncthreads();

        // --- S1: gather neighbor features + pos-MLP hidden, interleaved ---
#pragma unroll
        for (int kk2 = 0; kk2 < 2; kk2++) {
            int kk = k2 + kk2 * 8;
            int m  = ((int*)(SW + OFF_IDX))[pt * 16 + kk];
            const float* xr = x + ((size_t)b * NN + m) * CC + jc;
            float4 xa = *(const float4*)xr;
            float4 xb = *(const float4*)(xr + 4);
            float xv[8] = {xa.x, xa.y, xa.z, xa.w, xb.x, xb.y, xb.z, xb.w};
            const float* pdp = SW + OFF_PD + (pt * 16 + kk) * 4;
            float dx = pdp[0], dy = pdp[1], dz = pdp[2];
            float2* xh = (float2*)(SW + OFF_XH) + (pt * 16 + kk) * 64 + jc;
#pragma unroll
            for (int i = 0; i < 8; i++) {
                int j = jc + i;
                float hv = bp1[j];
                hv = fmaf(Wp1[j * 3 + 0], dx, hv);
                hv = fmaf(Wp1[j * 3 + 1], dy, hv);
                hv = fmaf(Wp1[j * 3 + 2], dz, hv);
                xh[i] = make_float2(xv[i], fmaxf(hv, 0.f));
            }
        }
        __syncthreads();

        // --- S2: main GEMMs (v, pe) with f32x2, + klog/qm side projections ---
        unsigned long long v0[4], v1[4], p0[4], p1[4];
#pragma unroll
        for (int i = 0; i < 4; i++) {
            v0[i] = pack2(bv[jc + 2 * i],  bv[jc + 2 * i + 1]);
            p0[i] = pack2(bp2[jc + 2 * i], bp2[jc + 2 * i + 1]);
            v1[i] = v0[i];
            p1[i] = p0[i];
        }
        float kl0 = 0.f, kl1 = 0.f, qmv = 0.f;
        const float2* xh0 = (const float2*)(SW + OFF_XH) + (pt * 16 + k2) * 64;
        const float2* xh1 = xh0 + 8 * 64;
#pragma unroll 8
        for (int c = 0; c < CC; c++) {
            float2 a0 = xh0[c];
            float2 a1 = xh1[c];
            ulonglong2 wva = *(const ulonglong2*)(SW + OFF_WVT + c * 64 + jc);
            ulonglong2 wvb = *(const ulonglong2*)(SW + OFF_WVT + c * 64 + jc + 4);
            ulonglong2 wpa = *(const ulonglong2*)(SW + OFF_WPT + c * 64 + jc);
            ulonglong2 wpb = *(const ulonglong2*)(SW + OFF_WPT + c * 64 + jc + 4);
            unsigned long long xd0 = pack2(a0.x, a0.x), hd0 = pack2(a0.y, a0.y);
            unsigned long long xd1 = pack2(a1.x, a1.x), hd1 = pack2(a1.y, a1.y);
            FMA2(v0[0], wva.x, xd0); FMA2(v0[1], wva.y, xd0);
            FMA2(v0[2], wvb.x, xd0); FMA2(v0[3], wvb.y, xd0);
            FMA2(v1[0], wva.x, xd1); FMA2(v1[1], wva.y, xd1);
            FMA2(v1[2], wvb.x, xd1); FMA2(v1[3], wvb.y, xd1);
            FMA2(p0[0], wpa.x, hd0); FMA2(p0[1], wpa.y, hd0);
            FMA2(p0[2], wpb.x, hd0); FMA2(p0[3], wpb.y, hd0);
            FMA2(p1[0], wpa.x, hd1); FMA2(p1[1], wpa.y, hd1);
            FMA2(p1[2], wpb.x, hd1); FMA2(p1[3], wpb.y, hd1);
            if (jg < 4) {
                float w = SW[OFF_WKM + c * 4 + jg];
                kl0 = fmaf(a0.x, w, kl0);
                kl1 = fmaf(a1.x, w, kl1);
            } else {
                qmv = fmaf(SW[OFF_XQ + pt * 64 + c], SW[OFF_WQM + c * 4 + (jg - 4)], qmv);
            }
        }
        if (jg < 4) {
            SW[OFF_KLOG + (pt * 16 + k2) * 4 + jg]     = kl0;
            SW[OFF_KLOG + (pt * 16 + k2 + 8) * 4 + jg] = kl1;
        } else if (k2 == 0) {
            SW[OFF_QM + pt * 4 + (jg - 4)] = qmv;
        }
        __syncthreads();

        // --- S3: per-head pe means + logits ---
        float s0 = 0.f, s1 = 0.f;
#pragma unroll
        for (int i = 0; i < 4; i++) {
            float2 u = unpack2(p0[i]); s0 += u.x + u.y;
            float2 w = unpack2(p1[i]); s1 += w.x + w.y;
        }
        s0 += __shfl_xor_sync(0xffffffffu, s0, 1);
        s1 += __shfl_xor_sync(0xffffffffu, s1, 1);
        if ((jg & 1) == 0) {
            float qb = SW[OFF_QM + pt * 4 + h0] + g_bqm[h0];
            float bk2 = g_bkm[h0];
            SW[OFF_LOG + (pt * 16 + k2) * 4 + h0] =
                qb - (SW[OFF_KLOG + (pt * 16 + k2) * 4 + h0] + bk2) + s0 * (1.f / 16.f);
            SW[OFF_LOG + (pt * 16 + k2 + 8) * 4 + h0] =
                qb - (SW[OFF_KLOG + (pt * 16 + k2 + 8) * 4 + h0] + bk2) + s1 * (1.f / 16.f);
        }
        __syncthreads();

        // --- S4: softmax over K per (point, head) ---
        if (t < 16) {
            int ptq = t >> 2, hh = t & 3;
            float mx = -3.402823466e+38f;
#pragma unroll
            for (int k = 0; k < KNN; k++)
                mx = fmaxf(mx, SW[OFF_LOG + (ptq * 16 + k) * 4 + hh]);
            float e[KNN]; float sum = 0.f;
#pragma unroll
            for (int k = 0; k < KNN; k++) {
                e[k] = __expf(SW[OFF_LOG + (ptq * 16 + k) * 4 + hh] - mx);
                sum += e[k];
            }
            float inv = 1.f / sum;
#pragma unroll
            for (int k = 0; k < KNN; k++)
                SW[OFF_ATTN + (ptq * 16 + k) * 4 + hh] = e[k] * inv;
        }
        __syncthreads();

        // --- S5: aggregate (scratch overlays XH region) ---
        {
            float w0 = SW[OFF_ATTN + (pt * 16 + k2) * 4 + h0];
            float w1 = SW[OFF_ATTN + (pt * 16 + k2 + 8) * 4 + h0];
            float part[8];
#pragma unroll
            for (int i = 0; i < 4; i++) {
                float2 a = unpack2(v0[i]), c = unpack2(p0[i]);
                float2 e = unpack2(v1[i]), f = unpack2(p1[i]);
                part[2 * i]     = w0 * (a.x + c.x) + w1 * (e.x + f.x);
                part[2 * i + 1] = w0 * (a.y + c.y) + w1 * (e.y + f.y);
            }
            float* RED = SW + OFF_XH + pt * 2048;
#pragma unroll
            for (int i = 0; i < 8; i++) RED[k2 * 64 + jc + i] = part[i];
        }
        __syncthreads();
        {
            float* RED = SW + OFF_XH + pt * 2048;
            float agg = 0.f;
#pragma unroll
            for (int g = 0; g < 8; g++) agg += RED[g * 64 + tp];
            RED[1024 + tp] = agg;
        }
        __syncthreads();

        // --- S6: fc + residual ---
        {
            const float* AGG = SW + OFF_XH + pt * 2048 + 1024;
            float a0 = bfc[tp], a1 = 0.f, a2 = 0.f, a3 = 0.f;
            const float4* wr = (const float4*)(Wfc + tp * CC);
#pragma unroll
            for (int c4 = 0; c4 < 16; c4 += 4) {
                float4 w0 = wr[c4],     w1 = wr[c4 + 1];
                float4 w2 = wr[c4 + 2], w3 = wr[c4 + 3];
                a0 = fmaf(w0.x, AGG[c4 * 4 + 0],  a0); a0 = fmaf(w0.y, AGG[c4 * 4 + 1],  a0);
                a0 = fmaf(w0.z, AGG[c4 * 4 + 2],  a0); a0 = fmaf(w0.w, AGG[c4 * 4 + 3],  a0);
                a1 = fmaf(w1.x, AGG[c4 * 4 + 4],  a1); a1 = fmaf(w1.y, AGG[c4 * 4 + 5],  a1);
                a1 = fmaf(w1.z, AGG[c4 * 4 + 6],  a1); a1 = fmaf(w1.w, AGG[c4 * 4 + 7],  a1);
                a2 = fmaf(w2.x, AGG[c4 * 4 + 8],  a2); a2 = fmaf(w2.y, AGG[c4 * 4 + 9],  a2);
                a2 = fmaf(w2.z, AGG[c4 * 4 + 10], a2); a2 = fmaf(w2.w, AGG[c4 * 4 + 11], a2);
                a3 = fmaf(w3.x, AGG[c4 * 4 + 12], a3); a3 = fmaf(w3.y, AGG[c4 * 4 + 13], a3);
                a3 = fmaf(w3.z, AGG[c4 * 4 + 14], a3); a3 = fmaf(w3.w, AGG[c4 * 4 + 15], a3);
            }
            out[(size_t)p * CC + tp] = SW[OFF_XQ + pt * 64 + tp] + ((a0 + a1) + (a2 + a3));
        }
        __syncthreads();   // protect smem reuse across rounds
    }
}

// ---------------- launch ----------------
extern "C" void kernel_launch(void* const* d_in, const int* in_sizes, int n_in,
                              void* d_out, int out_size) {
    const float* x   = (const float*)d_in[0];
    const float* pos = (const float*)d_in[1];
    const float* Wq  = (const float*)d_in[2];
    const float* bq  = (const float*)d_in[3];
    const float* Wk  = (const float*)d_in[4];
    const float* bk  = (const float*)d_in[5];
    const float* Wv  = (const float*)d_in[6];
    const float* bv  = (const float*)d_in[7];
    const float* Wp1 = (const float*)d_in[8];
    const float* bp1 = (const float*)d_in[9];
    const float* Wp2 = (const float*)d_in[10];
    const float* bp2 = (const float*)d_in[11];
    const float* Wfc = (const float*)d_in[12];
    const float* bfc = (const float*)d_in[13];
    float* out = (float*)d_out;

    // Unconditional (no static guards — determinism rule). Not a stream op,
    // so it is graph-capture-safe; idempotent across calls.
    cudaFuncSetAttribute(fused_kernel, cudaFuncAttributeMaxDynamicSharedMemorySize,
                         SMEM_FLOATS * 4);

    prep_kernel<<<16, 256>>>(Wq, Wk, Wv, Wp2, bq, bk);
    knn_part<<<BB * 32 * SEG, 128>>>(pos);
    knn_merge<<<(BB * NN) / 128, 128>>>();
    fused_kernel<<<(BB * NN) / 8, 256, SMEM_FLOATS * 4>>>(
        x, pos, bv, Wp1, bp1, bp2, Wfc, bfc, out);
}

// round 4
// speedup vs baseline: 3.2579x; 2.6361x over previous
#include <cuda_runtime.h>
#include <math.h>

#define BB   4
#define NN   4096
#define CC   64
#define KNN  16
#define NH   4
#define FULL 0xffffffffu
#define NEGINF (-3.402823466e+38f)

// ---------------- device scratch (allocation-free) ----------------
__device__ int    g_idx[BB * NN * KNN];
__device__ float4 g_PP [BB * NN];            // packed pos (x,y,z,|p|^2)
__device__ float  g_V  [BB * NN * CC];       // x @ Wv^T + bv
__device__ float  g_KL [BB * NN * NH];       // head-mean k logits (no bias)
__device__ float  g_QM [BB * NN * NH];       // head-mean q logits (no bias)
__device__ float  g_WvT [CC * CC];
__device__ float  g_WpT [CC * CC];           // Wp2 transposed [c][j]
__device__ float  g_WfcT[CC * CC];           // Wfc transposed [c][j]
__device__ float  g_Wkm [CC * NH];
__device__ float  g_Wqm [CC * NH];
__device__ float  g_Wpm [CC * NH];           // head-mean of Wp2 rows
__device__ float  g_PW1 [CC * 4];            // (Wp1 row, bp1) packed float4
__device__ float  g_CB  [NH];                // bqm - bkm + bpm

// ---------------- prep1: transposes + head-mean weights ----------------
__global__ void prep1_kernel(const float* __restrict__ Wq, const float* __restrict__ bq,
                             const float* __restrict__ Wk, const float* __restrict__ bk,
                             const float* __restrict__ Wv,
                             const float* __restrict__ Wp1, const float* __restrict__ bp1,
                             const float* __restrict__ Wp2, const float* __restrict__ bp2,
                             const float* __restrict__ Wfc) {
    int tg = blockIdx.x * 256 + threadIdx.x;   // 0..4095
    {   // transposes
        int r = tg >> 6, c = tg & 63;
        g_WvT [c * CC + r] = Wv [tg];
        g_WpT [c * CC + r] = Wp2[tg];
        g_WfcT[c * CC + r] = Wfc[tg];
    }
    if (blockIdx.x == 0) {
        int t = threadIdx.x;
        int c = t >> 2, h = t & 3;
        float sk = 0.f, sq = 0.f, sp = 0.f;
#pragma unroll
        for (int d = 0; d < 16; d++) {
            sk += Wk [(h * 16 + d) * CC + c];
            sq += Wq [(h * 16 + d) * CC + c];
            sp += Wp2[(h * 16 + d) * CC + c];
        }
        g_Wkm[c * NH + h] = sk * (1.f / 16.f);
        g_Wqm[c * NH + h] = sq * (1.f / 16.f);
        g_Wpm[c * NH + h] = sp * (1.f / 16.f);
        if (t < CC) {
            g_PW1[t * 4 + 0] = Wp1[t * 3 + 0];
            g_PW1[t * 4 + 1] = Wp1[t * 3 + 1];
            g_PW1[t * 4 + 2] = Wp1[t * 3 + 2];
            g_PW1[t * 4 + 3] = bp1[t];
        }
        if (t < NH) {
            float s1 = 0.f, s2 = 0.f, s3 = 0.f;
            for (int d = 0; d < 16; d++) {
                s1 += bq [t * 16 + d];
                s2 += bk [t * 16 + d];
                s3 += bp2[t * 16 + d];
            }
            g_CB[t] = (s1 - s2 + s3) * (1.f / 16.f);
        }
    }
}

// ---------------- prep2: per-point V, KL, QM, packed pos ----------------
__global__ __launch_bounds__(256) void prep2_kernel(const float* __restrict__ x,
                                                    const float* __restrict__ pos,
                                                    const float* __restrict__ bv) {
    __shared__ float xs[16 * CC];
    const int t = threadIdx.x;
    const int pbase = blockIdx.x * 16;              // 16 points per block

    ((float4*)xs)[t] = ((const float4*)(x + (size_t)pbase * CC))[t];
    __syncthreads();

    const int pt = t >> 4;
    const int jj = t & 15;
    const int p  = pbase + pt;
    const float* xr = xs + pt * CC;

    // V[p][j0..j0+3]
    float a0 = bv[jj * 4 + 0], a1 = bv[jj * 4 + 1],
          a2 = bv[jj * 4 + 2], a3 = bv[jj * 4 + 3];
#pragma unroll 8
    for (int c = 0; c < CC; c++) {
        float xv = xr[c];
        float4 w = ((const float4*)(g_WvT + c * CC))[jj];
        a0 = fmaf(xv, w.x, a0); a1 = fmaf(xv, w.y, a1);
        a2 = fmaf(xv, w.z, a2); a3 = fmaf(xv, w.w, a3);
    }
    ((float4*)(g_V + (size_t)p * CC))[jj] = make_float4(a0, a1, a2, a3);

    if (jj < 4) {               // KL[p][h]
        float s = 0.f;
#pragma unroll 8
        for (int c = 0; c < CC; c++) s = fmaf(xr[c], g_Wkm[c * 4 + jj], s);
        g_KL[(size_t)p * 4 + jj] = s;
    } else if (jj < 8) {        // QM[p][h]
        int h = jj - 4;
        float s = 0.f;
#pragma unroll 8
        for (int c = 0; c < CC; c++) s = fmaf(xr[c], g_Wqm[c * 4 + h], s);
        g_QM[(size_t)p * 4 + h] = s;
    } else if (jj == 8) {       // packed pos
        float px = pos[(size_t)p * 3 + 0];
        float py = pos[(size_t)p * 3 + 1];
        float pz = pos[(size_t)p * 3 + 2];
        float nn = px * px; nn = fmaf(py, py, nn); nn = fmaf(pz, pz, nn);
        g_PP[p] = make_float4(px, py, pz, nn);
    }
}

// ---------------- kNN: warp-per-query, warp-distributed top-16 ----------
__device__ __forceinline__ void warp_min16(float tv, int ti,
                                           float& mv, int& mI, int& ml) {
    mv = tv; mI = ti; ml = threadIdx.x & 31;
#pragma unroll
    for (int off = 1; off < 16; off <<= 1) {
        float ov = __shfl_xor_sync(FULL, mv, off);
        int   oi = __shfl_xor_sync(FULL, mI, off);
        int   ol = __shfl_xor_sync(FULL, ml, off);
        if (ov < mv || (ov == mv && oi > mI)) { mv = ov; mI = oi; ml = ol; }
    }
    mv = __shfl_sync(FULL, mv, 0);
    mI = __shfl_sync(FULL, mI, 0);
    ml = __shfl_sync(FULL, ml, 0);
}

__global__ __launch_bounds__(256) void knn_kernel() {
    const int wid  = threadIdx.x >> 5;
    const int lane = threadIdx.x & 31;
    const int q    = blockIdx.x * 8 + wid;
    const int b    = q >> 12;
    const float4* PPb = g_PP + (size_t)b * NN;

    float4 qp = PPb[q & 4095];

    float tv = NEGINF;
    int   ti = 0x7fffffff - lane;
    float wv = NEGINF;
    int   wm = 0x7fffffff;

    for (int mi0 = 0; mi0 < NN; mi0 += 32) {
        int mi = mi0 + lane;
        float4 c4 = PPb[mi];
        float inner = qp.x * c4.x;
        inner = fmaf(qp.y, c4.y, inner);
        inner = fmaf(qp.z, c4.z, inner);
        float d = 2.0f * inner - qp.w - c4.w;
        bool pred = (d > wv) || (d == wv && mi < wm);
        unsigned mask = __ballot_sync(FULL, pred);
        while (mask) {
            int src = __ffs(mask) - 1; mask &= mask - 1;
            float dc = __shfl_sync(FULL, d, src);
            int   mc = __shfl_sync(FULL, mi, src);
            float mv; int mI, ml;
            warp_min16(tv, ti, mv, mI, ml);
            if (dc > mv || (dc == mv && mc < mI)) {
                if (lane == ml) { tv = dc; ti = mc; }
                warp_min16(tv, ti, mv, mI, ml);   // refreshed threshold
            }
            wv = mv; wm = mI;
        }
    }
    if (lane < KNN) g_idx[(size_t)q * KNN + lane] = ti;
}

// ---------------- fused: warp-per-point, no block barriers --------------
#define HSTR 65
__global__ __launch_bounds__(256) void fused_kernel(
    const float* __restrict__ x,  const float* __restrict__ bp2,
    const float* __restrict__ bfc, float* __restrict__ out)
{
    __shared__ float hs   [8 * KNN * HSTR];   // relu hidden, per point
    __shared__ float attns[8 * KNN * NH];
    __shared__ float As   [8 * NH * CC];
    __shared__ float aggs [8 * CC];

    const int wid  = threadIdx.x >> 5;
    const int lane = threadIdx.x & 31;
    const int p    = blockIdx.x * 8 + wid;
    const int b    = p >> 12;

    float* hsb = hs    + wid * KNN * HSTR;
    float* atb = attns + wid * KNN * NH;
    float* Ab  = As    + wid * NH * CC;
    float* agb = aggs  + wid * CC;

    const int k    = lane >> 1;
    const int half = lane & 1;

    float rx0 = x[(size_t)p * CC + lane];
    float rx1 = x[(size_t)p * CC + lane + 32];
    float4 qp = g_PP[p];

    int m = 0;
    float4 kl4 = make_float4(0.f, 0.f, 0.f, 0.f);
    float pdx = 0.f, pdy = 0.f, pdz = 0.f;
    if (half == 0) {
        m = g_idx[(size_t)p * KNN + k];
        float4 np = g_PP[(size_t)b * NN + m];
        pdx = qp.x - np.x; pdy = qp.y - np.y; pdz = qp.z - np.z;
        kl4 = ((const float4*)g_KL)[(size_t)b * NN + m];
    }
    int src0 = lane & ~1;
    pdx = __shfl_sync(FULL, pdx, src0);
    pdy = __shfl_sync(FULL, pdy, src0);
    pdz = __shfl_sync(FULL, pdz, src0);

    float4 qm4 = ((const float4*)g_QM)[p];
    float4 cb4 = *(const float4*)g_CB;

    // hidden MLP + head-mean pe
    float mp0 = 0.f, mp1 = 0.f, mp2 = 0.f, mp3 = 0.f;
#pragma unroll 8
    for (int i = 0; i < 32; i++) {
        int c = half * 32 + i;
        float4 pw = ((const float4*)g_PW1)[c];
        float hv = fmaf(pw.x, pdx, fmaf(pw.y, pdy, fmaf(pw.z, pdz, pw.w)));
        float rh = fmaxf(hv, 0.f);
        hsb[k * HSTR + c] = rh;
        float4 wm4 = ((const float4*)g_Wpm)[c];
        mp0 = fmaf(rh, wm4.x, mp0); mp1 = fmaf(rh, wm4.y, mp1);
        mp2 = fmaf(rh, wm4.z, mp2); mp3 = fmaf(rh, wm4.w, mp3);
    }
    mp0 += __shfl_xor_sync(FULL, mp0, 1);
    mp1 += __shfl_xor_sync(FULL, mp1, 1);
    mp2 += __shfl_xor_sync(FULL, mp2, 1);
    mp3 += __shfl_xor_sync(FULL, mp3, 1);

    // logits (garbage on odd lanes, harmless) + softmax over 16 k
    float lg0 = qm4.x + cb4.x - kl4.x + mp0;
    float lg1 = qm4.y + cb4.y - kl4.y + mp1;
    float lg2 = qm4.z + cb4.z - kl4.z + mp2;
    float lg3 = qm4.w + cb4.w - kl4.w + mp3;
    float m0 = lg0, m1 = lg1, m2 = lg2, m3 = lg3;
#pragma unroll
    for (int off = 2; off < 32; off <<= 1) {
        m0 = fmaxf(m0, __shfl_xor_sync(FULL, m0, off));
        m1 = fmaxf(m1, __shfl_xor_sync(FULL, m1, off));
        m2 = fmaxf(m2, __shfl_xor_sync(FULL, m2, off));
        m3 = fmaxf(m3, __shfl_xor_sync(FULL, m3, off));
    }
    float e0 = __expf(lg0 - m0), e1 = __expf(lg1 - m1);
    float e2 = __expf(lg2 - m2), e3 = __expf(lg3 - m3);
    float s0 = e0, s1 = e1, s2 = e2, s3 = e3;
#pragma unroll
    for (int off = 2; off < 32; off <<= 1) {
        s0 += __shfl_xor_sync(FULL, s0, off);
        s1 += __shfl_xor_sync(FULL, s1, off);
        s2 += __shfl_xor_sync(FULL, s2, off);
        s3 += __shfl_xor_sync(FULL, s3, off);
    }
    if (half == 0)
        ((float4*)atb)[k] = make_float4(e0 / s0, e1 / s1, e2 / s2, e3 / s3);
    __syncwarp();

    // A[h][c] + attn-weighted V gather
    float A0[4] = {0.f, 0.f, 0.f, 0.f};
    float A1[4] = {0.f, 0.f, 0.f, 0.f};
    float av0 = 0.f, av1 = 0.f;
    bool lo = (lane < 16);
#pragma unroll
    for (int kk = 0; kk < KNN; kk++) {
        float4 a4 = ((const float4*)atb)[kk];
        float hv0 = hsb[kk * HSTR + lane];
        float hv1 = hsb[kk * HSTR + lane + 32];
        A0[0] = fmaf(a4.x, hv0, A0[0]); A0[1] = fmaf(a4.y, hv0, A0[1]);
        A0[2] = fmaf(a4.z, hv0, A0[2]); A0[3] = fmaf(a4.w, hv0, A0[3]);
        A1[0] = fmaf(a4.x, hv1, A1[0]); A1[1] = fmaf(a4.y, hv1, A1[1]);
        A1[2] = fmaf(a4.z, hv1, A1[2]); A1[3] = fmaf(a4.w, hv1, A1[3]);
        int mk = __shfl_sync(FULL, m, kk * 2);
        const float* vr = g_V + ((size_t)b * NN + mk) * CC;
        float aw0 = lo ? a4.x : a4.y;
        float aw1 = lo ? a4.z : a4.w;
        av0 = fmaf(aw0, vr[lane],      av0);
        av1 = fmaf(aw1, vr[lane + 32], av1);
    }
#pragma unroll
    for (int h = 0; h < 4; h++) {
        Ab[h * CC + lane]      = A0[h];
        Ab[h * CC + lane + 32] = A1[h];
    }
    __syncwarp();

    // agg[j] = av + bp2 + sum_c Wp2[j,c] * A[h_j, c]
    const int h0 = lane >> 4;
    const int h1 = 2 + h0;
    const float* A0r = Ab + h0 * CC;
    const float* A1r = Ab + h1 * CC;
    float acc0 = 0.f, acc1 = 0.f;
#pragma unroll 8
    for (int c = 0; c < CC; c++) {
        float w0 = g_WpT[c * CC + lane];
        float w1 = g_WpT[c * CC + lane + 32];
        acc0 = fmaf(w0, A0r[c], acc0);
        acc1 = fmaf(w1, A1r[c], acc1);
    }
    agb[lane]      = av0 + bp2[lane]      + acc0;
    agb[lane + 32] = av1 + bp2[lane + 32] + acc1;
    __syncwarp();

    // fc + residual
    float f0 = bfc[lane], f1 = bfc[lane + 32];
#pragma unroll 8
    for (int c = 0; c < CC; c++) {
        float ag = agb[c];
        f0 = fmaf(g_WfcT[c * CC + lane],      ag, f0);
        f1 = fmaf(g_WfcT[c * CC + lane + 32], ag, f1);
    }
    out[(size_t)p * CC + lane]      = rx0 + f0;
    out[(size_t)p * CC + lane + 32] = rx1 + f1;
}

// ---------------- launch ----------------
extern "C" void kernel_launch(void* const* d_in, const int* in_sizes, int n_in,
                              void* d_out, int out_size) {
    const float* x   = (const float*)d_in[0];
    const float* pos = (const float*)d_in[1];
    const float* Wq  = (const float*)d_in[2];
    const float* bq  = (const float*)d_in[3];
    const float* Wk  = (const float*)d_in[4];
    const float* bk  = (const float*)d_in[5];
    const float* Wv  = (const float*)d_in[6];
    const float* bv  = (const float*)d_in[7];
    const float* Wp1 = (const float*)d_in[8];
    const float* bp1 = (const float*)d_in[9];
    const float* Wp2 = (const float*)d_in[10];
    const float* bp2 = (const float*)d_in[11];
    const float* Wfc = (const float*)d_in[12];
    const float* bfc = (const float*)d_in[13];
    float* out = (float*)d_out;

    prep1_kernel<<<16, 256>>>(Wq, bq, Wk, bk, Wv, Wp1, bp1, Wp2, bp2, Wfc);
    prep2_kernel<<<(BB * NN) / 16, 256>>>(x, pos, bv);
    knn_kernel<<<(BB * NN) / 8, 256>>>();
    fused_kernel<<<(BB * NN) / 8, 256>>>(x, bp2, bfc, out);
}

// round 5
// speedup vs baseline: 4.3620x; 1.3389x over previous
#include <cuda_runtime.h>
#include <math.h>

#define BB   4
#define NN   4096
#define CC   64
#define KNN  16
#define NH   4
#define FULL 0xffffffffu
#define NEGINF (-3.402823466e+38f)

// ---------------- device scratch (allocation-free) ----------------
__device__ int    g_idx[BB * NN * KNN];
__device__ float4 g_PP [BB * NN];            // packed pos (x,y,z,|p|^2)
__device__ float  g_V  [BB * NN * CC];       // x @ Wv^T + bv
__device__ float  g_KL [BB * NN * NH];       // head-mean k logits (no bias)
__device__ float  g_QM [BB * NN * NH];       // head-mean q logits (no bias)
__device__ float  g_WvT [CC * CC];
__device__ float  g_WpT [CC * CC];           // Wp2 transposed [c][j]
__device__ float  g_WfcT[CC * CC];           // Wfc transposed [c][j]
__device__ float  g_Wkm [CC * NH];
__device__ float  g_Wqm [CC * NH];
__device__ float  g_Wpm [CC * NH];           // head-mean of Wp2 rows
__device__ float  g_PW1 [CC * 4];            // (Wp1 row, bp1) packed float4
__device__ float  g_CB  [NH];                // bqm - bkm + bpm

// ---------------- prep1: transposes + head-mean weights ----------------
__global__ void prep1_kernel(const float* __restrict__ Wq, const float* __restrict__ bq,
                             const float* __restrict__ Wk, const float* __restrict__ bk,
                             const float* __restrict__ Wv,
                             const float* __restrict__ Wp1, const float* __restrict__ bp1,
                             const float* __restrict__ Wp2, const float* __restrict__ bp2,
                             const float* __restrict__ Wfc) {
    int tg = blockIdx.x * 256 + threadIdx.x;   // 0..4095
    {   // transposes
        int r = tg >> 6, c = tg & 63;
        g_WvT [c * CC + r] = Wv [tg];
        g_WpT [c * CC + r] = Wp2[tg];
        g_WfcT[c * CC + r] = Wfc[tg];
    }
    if (blockIdx.x == 0) {
        int t = threadIdx.x;
        int c = t >> 2, h = t & 3;
        float sk = 0.f, sq = 0.f, sp = 0.f;
#pragma unroll
        for (int d = 0; d < 16; d++) {
            sk += Wk [(h * 16 + d) * CC + c];
            sq += Wq [(h * 16 + d) * CC + c];
            sp += Wp2[(h * 16 + d) * CC + c];
        }
        g_Wkm[c * NH + h] = sk * (1.f / 16.f);
        g_Wqm[c * NH + h] = sq * (1.f / 16.f);
        g_Wpm[c * NH + h] = sp * (1.f / 16.f);
        if (t < CC) {
            g_PW1[t * 4 + 0] = Wp1[t * 3 + 0];
            g_PW1[t * 4 + 1] = Wp1[t * 3 + 1];
            g_PW1[t * 4 + 2] = Wp1[t * 3 + 2];
            g_PW1[t * 4 + 3] = bp1[t];
        }
        if (t < NH) {
            float s1 = 0.f, s2 = 0.f, s3 = 0.f;
            for (int d = 0; d < 16; d++) {
                s1 += bq [t * 16 + d];
                s2 += bk [t * 16 + d];
                s3 += bp2[t * 16 + d];
            }
            g_CB[t] = (s1 - s2 + s3) * (1.f / 16.f);
        }
    }
}

// ---------------- prep2: per-point V, KL, QM, packed pos ----------------
__global__ __launch_bounds__(256) void prep2_kernel(const float* __restrict__ x,
                                                    const float* __restrict__ pos,
                                                    const float* __restrict__ bv) {
    __shared__ float xs[16 * CC];
    const int t = threadIdx.x;
    const int pbase = blockIdx.x * 16;              // 16 points per block

    ((float4*)xs)[t] = ((const float4*)(x + (size_t)pbase * CC))[t];
    __syncthreads();

    const int pt = t >> 4;
    const int jj = t & 15;
    const int p  = pbase + pt;
    const float* xr = xs + pt * CC;

    float a0 = bv[jj * 4 + 0], a1 = bv[jj * 4 + 1],
          a2 = bv[jj * 4 + 2], a3 = bv[jj * 4 + 3];
#pragma unroll 8
    for (int c = 0; c < CC; c++) {
        float xv = xr[c];
        float4 w = ((const float4*)(g_WvT + c * CC))[jj];
        a0 = fmaf(xv, w.x, a0); a1 = fmaf(xv, w.y, a1);
        a2 = fmaf(xv, w.z, a2); a3 = fmaf(xv, w.w, a3);
    }
    ((float4*)(g_V + (size_t)p * CC))[jj] = make_float4(a0, a1, a2, a3);

    if (jj < 4) {
        float s = 0.f;
#pragma unroll 8
        for (int c = 0; c < CC; c++) s = fmaf(xr[c], g_Wkm[c * 4 + jj], s);
        g_KL[(size_t)p * 4 + jj] = s;
    } else if (jj < 8) {
        int h = jj - 4;
        float s = 0.f;
#pragma unroll 8
        for (int c = 0; c < CC; c++) s = fmaf(xr[c], g_Wqm[c * 4 + h], s);
        g_QM[(size_t)p * 4 + h] = s;
    } else if (jj == 8) {
        float px = pos[(size_t)p * 3 + 0];
        float py = pos[(size_t)p * 3 + 1];
        float pz = pos[(size_t)p * 3 + 2];
        float nn = px * px; nn = fmaf(py, py, nn); nn = fmaf(pz, pz, nn);
        g_PP[p] = make_float4(px, py, pz, nn);
    }
}

// ---------------- kNN helpers ----------------
__device__ __forceinline__ void warp_min16(float tv, int ti,
                                           float& mv, int& mI, int& ml) {
    mv = tv; mI = ti; ml = threadIdx.x & 31;
#pragma unroll
    for (int off = 1; off < 16; off <<= 1) {
        float ov = __shfl_xor_sync(FULL, mv, off);
        int   oi = __shfl_xor_sync(FULL, mI, off);
        int   ol = __shfl_xor_sync(FULL, ml, off);
        if (ov < mv || (ov == mv && oi > mI)) { mv = ov; mI = oi; ml = ol; }
    }
    mv = __shfl_sync(FULL, mv, 0);
    mI = __shfl_sync(FULL, mI, 0);
    ml = __shfl_sync(FULL, ml, 0);
}

// ---------------- kNN: warp/query, per-lane sorted top-5, smem tiles ------
__global__ __launch_bounds__(256) void knn_kernel() {
    __shared__ float4 cand[256];
    const int wid  = threadIdx.x >> 5;
    const int lane = threadIdx.x & 31;
    const int q    = blockIdx.x * 8 + wid;   // 8 queries per block, same batch
    const int b    = q >> 12;
    const float4* PPb = g_PP + (size_t)b * NN;

    const float4 qp = PPb[q & 4095];

    // per-lane sorted top-5 (v0 >= v1 >= ... >= v4), static registers only
    float v0 = NEGINF, v1 = NEGINF, v2 = NEGINF, v3 = NEGINF, v4 = NEGINF;
    int   i0 = 0x7fff0000 + lane * 8,     i1 = i0 + 1, i2 = i0 + 2,
          i3 = i0 + 3,                    i4 = i0 + 4;

    for (int tile = 0; tile < NN / 256; tile++) {
        cand[threadIdx.x] = PPb[tile * 256 + threadIdx.x];
        __syncthreads();
#pragma unroll
        for (int j = 0; j < 256; j += 32) {
            float4 c4 = cand[j + lane];
            int mi = tile * 256 + j + lane;
            float inner = qp.x * c4.x;
            inner = fmaf(qp.y, c4.y, inner);
            inner = fmaf(qp.z, c4.z, inner);
            float d = 2.0f * inner - qp.w - c4.w;
            if (d > v4) {                     // insert + bubble (static idx)
                v4 = d; i4 = mi;
                if (v4 > v3) { float tv = v3; v3 = v4; v4 = tv; int ti = i3; i3 = i4; i4 = ti; }
                if (v3 > v2) { float tv = v2; v2 = v3; v3 = tv; int ti = i2; i2 = i3; i3 = ti; }
                if (v2 > v1) { float tv = v1; v1 = v2; v2 = tv; int ti = i1; i1 = i2; i2 = ti; }
                if (v1 > v0) { float tv = v0; v0 = v1; v1 = tv; int ti = i0; i0 = i1; i1 = ti; }
            }
        }
        __syncthreads();
    }

    // merge: 16 warp-argmax pops over the 32 sorted lane-lists
    int popped = 0;
#pragma unroll
    for (int s = 0; s < KNN; s++) {
        float bvv = v0; int bii = i0;
#pragma unroll
        for (int off = 16; off >= 1; off >>= 1) {
            float ov = __shfl_xor_sync(FULL, bvv, off);
            int   oi = __shfl_xor_sync(FULL, bii, off);
            if (ov > bvv || (ov == bvv && oi < bii)) { bvv = ov; bii = oi; }
        }
        if (v0 == bvv && i0 == bii) {        // unique winner (idx unique)
            popped++;
            v0 = v1; i0 = i1; v1 = v2; i1 = i2;
            v2 = v3; i2 = i3; v3 = v4; i3 = i4;
            v4 = NEGINF; i4 = 0x7ffffff0 + lane;
        }
        if (lane == 0) g_idx[(size_t)q * KNN + s] = bii;
    }

    // rare exact fallback: a lane saturated all 5 slots into the top-16
    if (__ballot_sync(FULL, popped >= 5)) {
        float tv = NEGINF; int ti = 0x7fffffff - lane;
        float wv = NEGINF; int wm = 0x7fffffff;
        for (int mi0 = 0; mi0 < NN; mi0 += 32) {
            int mi = mi0 + lane;
            float4 c4 = PPb[mi];
            float inner = qp.x * c4.x;
            inner = fmaf(qp.y, c4.y, inner);
            inner = fmaf(qp.z, c4.z, inner);
            float d = 2.0f * inner - qp.w - c4.w;
            bool pred = (d > wv) || (d == wv && mi < wm);
            unsigned mask = __ballot_sync(FULL, pred);
            while (mask) {
                int src = __ffs(mask) - 1; mask &= mask - 1;
                float dc = __shfl_sync(FULL, d, src);
                int   mc = __shfl_sync(FULL, mi, src);
                float mv; int mI, ml;
                warp_min16(tv, ti, mv, mI, ml);
                if (dc > mv || (dc == mv && mc < mI)) {
                    if (lane == ml) { tv = dc; ti = mc; }
                    warp_min16(tv, ti, mv, mI, ml);
                }
                wv = mv; wm = mI;
            }
        }
        if (lane < KNN) g_idx[(size_t)q * KNN + lane] = ti;
    }
}

// ---------------- fused: warp-per-point (unchanged from R4) --------------
#define HSTR 65
__global__ __launch_bounds__(256) void fused_kernel(
    const float* __restrict__ x,  const float* __restrict__ bp2,
    const float* __restrict__ bfc, float* __restrict__ out)
{
    __shared__ float hs   [8 * KNN * HSTR];
    __shared__ float attns[8 * KNN * NH];
    __shared__ float As   [8 * NH * CC];
    __shared__ float aggs [8 * CC];

    const int wid  = threadIdx.x >> 5;
    const int lane = threadIdx.x & 31;
    const int p    = blockIdx.x * 8 + wid;
    const int b    = p >> 12;

    float* hsb = hs    + wid * KNN * HSTR;
    float* atb = attns + wid * KNN * NH;
    float* Ab  = As    + wid * NH * CC;
    float* agb = aggs  + wid * CC;

    const int k    = lane >> 1;
    const int half = lane & 1;

    float rx0 = x[(size_t)p * CC + lane];
    float rx1 = x[(size_t)p * CC + lane + 32];
    float4 qp = g_PP[p];

    int m = 0;
    float4 kl4 = make_float4(0.f, 0.f, 0.f, 0.f);
    float pdx = 0.f, pdy = 0.f, pdz = 0.f;
    if (half == 0) {
        m = g_idx[(size_t)p * KNN + k];
        float4 np = g_PP[(size_t)b * NN + m];
        pdx = qp.x - np.x; pdy = qp.y - np.y; pdz = qp.z - np.z;
        kl4 = ((const float4*)g_KL)[(size_t)b * NN + m];
    }
    int src0 = lane & ~1;
    pdx = __shfl_sync(FULL, pdx, src0);
    pdy = __shfl_sync(FULL, pdy, src0);
    pdz = __shfl_sync(FULL, pdz, src0);

    float4 qm4 = ((const float4*)g_QM)[p];
    float4 cb4 = *(const float4*)g_CB;

    float mp0 = 0.f, mp1 = 0.f, mp2 = 0.f, mp3 = 0.f;
#pragma unroll 8
    for (int i = 0; i < 32; i++) {
        int c = half * 32 + i;
        float4 pw = ((const float4*)g_PW1)[c];
        float hv = fmaf(pw.x, pdx, fmaf(pw.y, pdy, fmaf(pw.z, pdz, pw.w)));
        float rh = fmaxf(hv, 0.f);
        hsb[k * HSTR + c] = rh;
        float4 wm4 = ((const float4*)g_Wpm)[c];
        mp0 = fmaf(rh, wm4.x, mp0); mp1 = fmaf(rh, wm4.y, mp1);
        mp2 = fmaf(rh, wm4.z, mp2); mp3 = fmaf(rh, wm4.w, mp3);
    }
    mp0 += __shfl_xor_sync(FULL, mp0, 1);
    mp1 += __shfl_xor_sync(FULL, mp1, 1);
    mp2 += __shfl_xor_sync(FULL, mp2, 1);
    mp3 += __shfl_xor_sync(FULL, mp3, 1);

    float lg0 = qm4.x + cb4.x - kl4.x + mp0;
    float lg1 = qm4.y + cb4.y - kl4.y + mp1;
    float lg2 = qm4.z + cb4.z - kl4.z + mp2;
    float lg3 = qm4.w + cb4.w - kl4.w + mp3;
    float m0 = lg0, m1 = lg1, m2 = lg2, m3 = lg3;
#pragma unroll
    for (int off = 2; off < 32; off <<= 1) {
        m0 = fmaxf(m0, __shfl_xor_sync(FULL, m0, off));
        m1 = fmaxf(m1, __shfl_xor_sync(FULL, m1, off));
        m2 = fmaxf(m2, __shfl_xor_sync(FULL, m2, off));
        m3 = fmaxf(m3, __shfl_xor_sync(FULL, m3, off));
    }
    float e0 = __expf(lg0 - m0), e1 = __expf(lg1 - m1);
    float e2 = __expf(lg2 - m2), e3 = __expf(lg3 - m3);
    float s0 = e0, s1 = e1, s2 = e2, s3 = e3;
#pragma unroll
    for (int off = 2; off < 32; off <<= 1) {
        s0 += __shfl_xor_sync(FULL, s0, off);
        s1 += __shfl_xor_sync(FULL, s1, off);
        s2 += __shfl_xor_sync(FULL, s2, off);
        s3 += __shfl_xor_sync(FULL, s3, off);
    }
    if (half == 0)
        ((float4*)atb)[k] = make_float4(e0 / s0, e1 / s1, e2 / s2, e3 / s3);
    __syncwarp();

    float A0[4] = {0.f, 0.f, 0.f, 0.f};
    float A1[4] = {0.f, 0.f, 0.f, 0.f};
    float av0 = 0.f, av1 = 0.f;
    bool lo = (lane < 16);
#pragma unroll
    for (int kk = 0; kk < KNN; kk++) {
        float4 a4 = ((const float4*)atb)[kk];
        float hv0 = hsb[kk * HSTR + lane];
        float hv1 = hsb[kk * HSTR + lane + 32];
        A0[0] = fmaf(a4.x, hv0, A0[0]); A0[1] = fmaf(a4.y, hv0, A0[1]);
        A0[2] = fmaf(a4.z, hv0, A0[2]); A0[3] = fmaf(a4.w, hv0, A0[3]);
        A1[0] = fmaf(a4.x, hv1, A1[0]); A1[1] = fmaf(a4.y, hv1, A1[1]);
        A1[2] = fmaf(a4.z, hv1, A1[2]); A1[3] = fmaf(a4.w, hv1, A1[3]);
        int mk = __shfl_sync(FULL, m, kk * 2);
        const float* vr = g_V + ((size_t)b * NN + mk) * CC;
        float aw0 = lo ? a4.x : a4.y;
        float aw1 = lo ? a4.z : a4.w;
        av0 = fmaf(aw0, vr[lane],      av0);
        av1 = fmaf(aw1, vr[lane + 32], av1);
    }
#pragma unroll
    for (int h = 0; h < 4; h++) {
        Ab[h * CC + lane]      = A0[h];
        Ab[h * CC + lane + 32] = A1[h];
    }
    __syncwarp();

    const int h0 = lane >> 4;
    const int h1 = 2 + h0;
    const float* A0r = Ab + h0 * CC;
    const float* A1r = Ab + h1 * CC;
    float acc0 = 0.f, acc1 = 0.f;
#pragma unroll 8
    for (int c = 0; c < CC; c++) {
        float w0 = g_WpT[c * CC + lane];
        float w1 = g_WpT[c * CC + lane + 32];
        acc0 = fmaf(w0, A0r[c], acc0);
        acc1 = fmaf(w1, A1r[c], acc1);
    }
    agb[lane]      = av0 + bp2[lane]      + acc0;
    agb[lane + 32] = av1 + bp2[lane + 32] + acc1;
    __syncwarp();

    float f0 = bfc[lane], f1 = bfc[lane + 32];
#pragma unroll 8
    for (int c = 0; c < CC; c++) {
        float ag = agb[c];
        f0 = fmaf(g_WfcT[c * CC + lane],      ag, f0);
        f1 = fmaf(g_WfcT[c * CC + lane + 32], ag, f1);
    }
    out[(size_t)p * CC + lane]      = rx0 + f0;
    out[(size_t)p * CC + lane + 32] = rx1 + f1;
}

// ---------------- launch ----------------
extern "C" void kernel_launch(void* const* d_in, const int* in_sizes, int n_in,
                              void* d_out, int out_size) {
    const float* x   = (const float*)d_in[0];
    const float* pos = (const float*)d_in[1];
    const float* Wq  = (const float*)d_in[2];
    const float* bq  = (const float*)d_in[3];
    const float* Wk  = (const float*)d_in[4];
    const float* bk  = (const float*)d_in[5];
    const float* Wv  = (const float*)d_in[6];
    const float* bv  = (const float*)d_in[7];
    const float* Wp1 = (const float*)d_in[8];
    const float* bp1 = (const float*)d_in[9];
    const float* Wp2 = (const float*)d_in[10];
    const float* bp2 = (const float*)d_in[11];
    const float* Wfc = (const float*)d_in[12];
    const float* bfc = (const float*)d_in[13];
    float* out = (float*)d_out;

    prep1_kernel<<<16, 256>>>(Wq, bq, Wk, bk, Wv, Wp1, bp1, Wp2, bp2, Wfc);
    prep2_kernel<<<(BB * NN) / 16, 256>>>(x, pos, bv);
    knn_kernel<<<(BB * NN) / 8, 256>>>();
    fused_kernel<<<(BB * NN) / 8, 256>>>(x, bp2, bfc, out);
}

// round 6
// speedup vs baseline: 4.5314x; 1.0388x over previous
#include <cuda_runtime.h>
#include <math.h>

#define BB   4
#define NN   4096
#define CC   64
#define KNN  16
#define NH   4
#define FULL 0xffffffffu
#define NEGINF (-3.402823466e+38f)

// ---------------- device scratch (allocation-free) ----------------
__device__ int    g_idx[BB * NN * KNN];
__device__ float4 g_PP [BB * NN];            // packed pos (x,y,z,|p|^2)
__device__ float  g_V  [BB * NN * CC];       // x @ Wv^T + bv
__device__ float  g_KL [BB * NN * NH];       // head-mean k logits (no bias)
__device__ float  g_QM [BB * NN * NH];       // head-mean q logits (no bias)
__device__ float  g_WvT [CC * CC];
__device__ float  g_WpT [CC * CC];           // Wp2 transposed [c][j]
__device__ float  g_WfcT[CC * CC];           // Wfc transposed [c][j]
__device__ float  g_Wkm [CC * NH];
__device__ float  g_Wqm [CC * NH];
__device__ float  g_Wpm [CC * NH];           // head-mean of Wp2 rows
__device__ float  g_PW1 [CC * 4];            // (Wp1 row, bp1) packed float4
__device__ float  g_CB  [NH];                // bqm - bkm + bpm

// ---------------- prep1 ----------------
__global__ void prep1_kernel(const float* __restrict__ Wq, const float* __restrict__ bq,
                             const float* __restrict__ Wk, const float* __restrict__ bk,
                             const float* __restrict__ Wv,
                             const float* __restrict__ Wp1, const float* __restrict__ bp1,
                             const float* __restrict__ Wp2, const float* __restrict__ bp2,
                             const float* __restrict__ Wfc) {
    int tg = blockIdx.x * 256 + threadIdx.x;
    {
        int r = tg >> 6, c = tg & 63;
        g_WvT [c * CC + r] = Wv [tg];
        g_WpT [c * CC + r] = Wp2[tg];
        g_WfcT[c * CC + r] = Wfc[tg];
    }
    if (blockIdx.x == 0) {
        int t = threadIdx.x;
        int c = t >> 2, h = t & 3;
        float sk = 0.f, sq = 0.f, sp = 0.f;
#pragma unroll
        for (int d = 0; d < 16; d++) {
            sk += Wk [(h * 16 + d) * CC + c];
            sq += Wq [(h * 16 + d) * CC + c];
            sp += Wp2[(h * 16 + d) * CC + c];
        }
        g_Wkm[c * NH + h] = sk * (1.f / 16.f);
        g_Wqm[c * NH + h] = sq * (1.f / 16.f);
        g_Wpm[c * NH + h] = sp * (1.f / 16.f);
        if (t < CC) {
            g_PW1[t * 4 + 0] = Wp1[t * 3 + 0];
            g_PW1[t * 4 + 1] = Wp1[t * 3 + 1];
            g_PW1[t * 4 + 2] = Wp1[t * 3 + 2];
            g_PW1[t * 4 + 3] = bp1[t];
        }
        if (t < NH) {
            float s1 = 0.f, s2 = 0.f, s3 = 0.f;
            for (int d = 0; d < 16; d++) {
                s1 += bq [t * 16 + d];
                s2 += bk [t * 16 + d];
                s3 += bp2[t * 16 + d];
            }
            g_CB[t] = (s1 - s2 + s3) * (1.f / 16.f);
        }
    }
}

// ---------------- prep2 ----------------
__global__ __launch_bounds__(256) void prep2_kernel(const float* __restrict__ x,
                                                    const float* __restrict__ pos,
                                                    const float* __restrict__ bv) {
    __shared__ float xs[16 * CC];
    const int t = threadIdx.x;
    const int pbase = blockIdx.x * 16;

    ((float4*)xs)[t] = ((const float4*)(x + (size_t)pbase * CC))[t];
    __syncthreads();

    const int pt = t >> 4;
    const int jj = t & 15;
    const int p  = pbase + pt;
    const float* xr = xs + pt * CC;

    float a0 = bv[jj * 4 + 0], a1 = bv[jj * 4 + 1],
          a2 = bv[jj * 4 + 2], a3 = bv[jj * 4 + 3];
#pragma unroll 8
    for (int c = 0; c < CC; c++) {
        float xv = xr[c];
        float4 w = ((const float4*)(g_WvT + c * CC))[jj];
        a0 = fmaf(xv, w.x, a0); a1 = fmaf(xv, w.y, a1);
        a2 = fmaf(xv, w.z, a2); a3 = fmaf(xv, w.w, a3);
    }
    ((float4*)(g_V + (size_t)p * CC))[jj] = make_float4(a0, a1, a2, a3);

    if (jj < 4) {
        float s = 0.f;
#pragma unroll 8
        for (int c = 0; c < CC; c++) s = fmaf(xr[c], g_Wkm[c * 4 + jj], s);
        g_KL[(size_t)p * 4 + jj] = s;
    } else if (jj < 8) {
        int h = jj - 4;
        float s = 0.f;
#pragma unroll 8
        for (int c = 0; c < CC; c++) s = fmaf(xr[c], g_Wqm[c * 4 + h], s);
        g_QM[(size_t)p * 4 + h] = s;
    } else if (jj == 8) {
        float px = pos[(size_t)p * 3 + 0];
        float py = pos[(size_t)p * 3 + 1];
        float pz = pos[(size_t)p * 3 + 2];
        float nn = px * px; nn = fmaf(py, py, nn); nn = fmaf(pz, pz, nn);
        g_PP[p] = make_float4(px, py, pz, nn);
    }
}

// ---------------- kNN helpers ----------------
__device__ __forceinline__ void warp_min16(float tv, int ti,
                                           float& mv, int& mI, int& ml) {
    mv = tv; mI = ti; ml = threadIdx.x & 31;
#pragma unroll
    for (int off = 1; off < 16; off <<= 1) {
        float ov = __shfl_xor_sync(FULL, mv, off);
        int   oi = __shfl_xor_sync(FULL, mI, off);
        int   ol = __shfl_xor_sync(FULL, ml, off);
        if (ov < mv || (ov == mv && oi > mI)) { mv = ov; mI = oi; ml = ol; }
    }
    mv = __shfl_sync(FULL, mv, 0);
    mI = __shfl_sync(FULL, mI, 0);
    ml = __shfl_sync(FULL, ml, 0);
}

// ---------------- kNN: warp/query, branchless per-lane top-5, direct LDG ---
__global__ __launch_bounds__(256) void knn_kernel() {
    const int wid  = threadIdx.x >> 5;
    const int lane = threadIdx.x & 31;
    const int q    = blockIdx.x * 8 + wid;
    const int b    = q >> 12;
    const float4* PPb = g_PP + (size_t)b * NN;

    const float4 qp = PPb[q & 4095];
    const float  qw = -qp.w;

    // per-lane sorted top-5 (v0 >= ... >= v4), static registers only
    float v0 = NEGINF, v1 = NEGINF, v2 = NEGINF, v3 = NEGINF, v4 = NEGINF;
    int   i0 = 0x7fff0000 + lane * 8, i1 = i0 + 1, i2 = i0 + 2,
          i3 = i0 + 3,                i4 = i0 + 4;

#pragma unroll 2
    for (int mi0 = 0; mi0 < NN; mi0 += 32) {
        int mi = mi0 + lane;
        float4 c4 = __ldg(&PPb[mi]);
        float inner = qp.x * c4.x;
        inner = fmaf(qp.y, c4.y, inner);
        inner = fmaf(qp.z, c4.z, inner);
        float d = fmaf(2.0f, inner, qw - c4.w);
        if (d > v4) {
            // branchless predicated bubble (no internal branches)
            float u = d; int ui = mi;
            bool c;
            c = u > v3; v4 = c ? v3 : u; i4 = c ? i3 : ui;
                        v3 = c ? u  : v3; i3 = c ? ui : i3;
            c = v3 > v2; { float tv = v2; v2 = c ? v3 : v2; v3 = c ? tv : v3; }
                         { int ti = i2;   i2 = c ? i3 : i2; i3 = c ? ti : i3; }
            c = v2 > v1; { float tv = v1; v1 = c ? v2 : v1; v2 = c ? tv : v2; }
                         { int ti = i1;   i1 = c ? i2 : i1; i2 = c ? ti : i2; }
            c = v1 > v0; { float tv = v0; v0 = c ? v1 : v0; v1 = c ? tv : v1; }
                         { int ti = i0;   i0 = c ? i1 : i0; i1 = c ? ti : i1; }
        }
    }

    // merge: 16 warp-argmax pops over the 32 sorted lane-lists
    int popped = 0;
#pragma unroll
    for (int s = 0; s < KNN; s++) {
        float bvv = v0; int bii = i0;
#pragma unroll
        for (int off = 16; off >= 1; off >>= 1) {
            float ov = __shfl_xor_sync(FULL, bvv, off);
            int   oi = __shfl_xor_sync(FULL, bii, off);
            if (ov > bvv || (ov == bvv && oi < bii)) { bvv = ov; bii = oi; }
        }
        if (v0 == bvv && i0 == bii) {
            popped++;
            v0 = v1; i0 = i1; v1 = v2; i1 = i2;
            v2 = v3; i2 = i3; v3 = v4; i3 = i4;
            v4 = NEGINF; i4 = 0x7ffffff0 + lane;
        }
        if (lane == 0) g_idx[(size_t)q * KNN + s] = bii;
    }

    // rare exact fallback: a lane saturated all 5 slots into the top-16
    if (__ballot_sync(FULL, popped >= 5)) {
        float tv = NEGINF; int ti = 0x7fffffff - lane;
        float wv = NEGINF; int wm = 0x7fffffff;
        for (int mi0 = 0; mi0 < NN; mi0 += 32) {
            int mi = mi0 + lane;
            float4 c4 = PPb[mi];
            float inner = qp.x * c4.x;
            inner = fmaf(qp.y, c4.y, inner);
            inner = fmaf(qp.z, c4.z, inner);
            float d = 2.0f * inner - qp.w - c4.w;
            bool pred = (d > wv) || (d == wv && mi < wm);
            unsigned mask = __ballot_sync(FULL, pred);
            while (mask) {
                int src = __ffs(mask) - 1; mask &= mask - 1;
                float dc = __shfl_sync(FULL, d, src);
                int   mc = __shfl_sync(FULL, mi, src);
                float mv; int mI, ml;
                warp_min16(tv, ti, mv, mI, ml);
                if (dc > mv || (dc == mv && mc < mI)) {
                    if (lane == ml) { tv = dc; ti = mc; }
                    warp_min16(tv, ti, mv, mI, ml);
                }
                wv = mv; wm = mI;
            }
        }
        if (lane < KNN) g_idx[(size_t)q * KNN + lane] = ti;
    }
}

// ---------------- fused: warp-per-point (unchanged) --------------
#define HSTR 65
__global__ __launch_bounds__(256) void fused_kernel(
    const float* __restrict__ x,  const float* __restrict__ bp2,
    const float* __restrict__ bfc, float* __restrict__ out)
{
    __shared__ float hs   [8 * KNN * HSTR];
    __shared__ float attns[8 * KNN * NH];
    __shared__ float As   [8 * NH * CC];
    __shared__ float aggs [8 * CC];

    const int wid  = threadIdx.x >> 5;
    const int lane = threadIdx.x & 31;
    const int p    = blockIdx.x * 8 + wid;
    const int b    = p >> 12;

    float* hsb = hs    + wid * KNN * HSTR;
    float* atb = attns + wid * KNN * NH;
    float* Ab  = As    + wid * NH * CC;
    float* agb = aggs  + wid * CC;

    const int k    = lane >> 1;
    const int half = lane & 1;

    float rx0 = x[(size_t)p * CC + lane];
    float rx1 = x[(size_t)p * CC + lane + 32];
    float4 qp = g_PP[p];

    int m = 0;
    float4 kl4 = make_float4(0.f, 0.f, 0.f, 0.f);
    float pdx = 0.f, pdy = 0.f, pdz = 0.f;
    if (half == 0) {
        m = g_idx[(size_t)p * KNN + k];
        float4 np = g_PP[(size_t)b * NN + m];
        pdx = qp.x - np.x; pdy = qp.y - np.y; pdz = qp.z - np.z;
        kl4 = ((const float4*)g_KL)[(size_t)b * NN + m];
    }
    int src0 = lane & ~1;
    pdx = __shfl_sync(FULL, pdx, src0);
    pdy = __shfl_sync(FULL, pdy, src0);
    pdz = __shfl_sync(FULL, pdz, src0);

    float4 qm4 = ((const float4*)g_QM)[p];
    float4 cb4 = *(const float4*)g_CB;

    float mp0 = 0.f, mp1 = 0.f, mp2 = 0.f, mp3 = 0.f;
#pragma unroll 8
    for (int i = 0; i < 32; i++) {
        int c = half * 32 + i;
        float4 pw = ((const float4*)g_PW1)[c];
        float hv = fmaf(pw.x, pdx, fmaf(pw.y, pdy, fmaf(pw.z, pdz, pw.w)));
        float rh = fmaxf(hv, 0.f);
        hsb[k * HSTR + c] = rh;
        float4 wm4 = ((const float4*)g_Wpm)[c];
        mp0 = fmaf(rh, wm4.x, mp0); mp1 = fmaf(rh, wm4.y, mp1);
        mp2 = fmaf(rh, wm4.z, mp2); mp3 = fmaf(rh, wm4.w, mp3);
    }
    mp0 += __shfl_xor_sync(FULL, mp0, 1);
    mp1 += __shfl_xor_sync(FULL, mp1, 1);
    mp2 += __shfl_xor_sync(FULL, mp2, 1);
    mp3 += __shfl_xor_sync(FULL, mp3, 1);

    float lg0 = qm4.x + cb4.x - kl4.x + mp0;
    float lg1 = qm4.y + cb4.y - kl4.y + mp1;
    float lg2 = qm4.z + cb4.z - kl4.z + mp2;
    float lg3 = qm4.w + cb4.w - kl4.w + mp3;
    float m0 = lg0, m1 = lg1, m2 = lg2, m3 = lg3;
#pragma unroll
    for (int off = 2; off < 32; off <<= 1) {
        m0 = fmaxf(m0, __shfl_xor_sync(FULL, m0, off));
        m1 = fmaxf(m1, __shfl_xor_sync(FULL, m1, off));
        m2 = fmaxf(m2, __shfl_xor_sync(FULL, m2, off));
        m3 = fmaxf(m3, __shfl_xor_sync(FULL, m3, off));
    }
    float e0 = __expf(lg0 - m0), e1 = __expf(lg1 - m1);
    float e2 = __expf(lg2 - m2), e3 = __expf(lg3 - m3);
    float s0 = e0, s1 = e1, s2 = e2, s3 = e3;
#pragma unroll
    for (int off = 2; off < 32; off <<= 1) {
        s0 += __shfl_xor_sync(FULL, s0, off);
        s1 += __shfl_xor_sync(FULL, s1, off);
        s2 += __shfl_xor_sync(FULL, s2, off);
        s3 += __shfl_xor_sync(FULL, s3, off);
    }
    if (half == 0)
        ((float4*)atb)[k] = make_float4(e0 / s0, e1 / s1, e2 / s2, e3 / s3);
    __syncwarp();

    float A0[4] = {0.f, 0.f, 0.f, 0.f};
    float A1[4] = {0.f, 0.f, 0.f, 0.f};
    float av0 = 0.f, av1 = 0.f;
    bool lo = (lane < 16);
#pragma unroll
    for (int kk = 0; kk < KNN; kk++) {
        float4 a4 = ((const float4*)atb)[kk];
        float hv0 = hsb[kk * HSTR + lane];
        float hv1 = hsb[kk * HSTR + lane + 32];
        A0[0] = fmaf(a4.x, hv0, A0[0]); A0[1] = fmaf(a4.y, hv0, A0[1]);
        A0[2] = fmaf(a4.z, hv0, A0[2]); A0[3] = fmaf(a4.w, hv0, A0[3]);
        A1[0] = fmaf(a4.x, hv1, A1[0]); A1[1] = fmaf(a4.y, hv1, A1[1]);
        A1[2] = fmaf(a4.z, hv1, A1[2]); A1[3] = fmaf(a4.w, hv1, A1[3]);
        int mk = __shfl_sync(FULL, m, kk * 2);
        const float* vr = g_V + ((size_t)b * NN + mk) * CC;
        float aw0 = lo ? a4.x : a4.y;
        float aw1 = lo ? a4.z : a4.w;
        av0 = fmaf(aw0, vr[lane],      av0);
        av1 = fmaf(aw1, vr[lane + 32], av1);
    }
#pragma unroll
    for (int h = 0; h < 4; h++) {
        Ab[h * CC + lane]      = A0[h];
        Ab[h * CC + lane + 32] = A1[h];
    }
    __syncwarp();

    const int h0 = lane >> 4;
    const int h1 = 2 + h0;
    const float* A0r = Ab + h0 * CC;
    const float* A1r = Ab + h1 * CC;
    float acc0 = 0.f, acc1 = 0.f;
#pragma unroll 8
    for (int c = 0; c < CC; c++) {
        float w0 = g_WpT[c * CC + lane];
        float w1 = g_WpT[c * CC + lane + 32];
        acc0 = fmaf(w0, A0r[c], acc0);
        acc1 = fmaf(w1, A1r[c], acc1);
    }
    agb[lane]      = av0 + bp2[lane]      + acc0;
    agb[lane + 32] = av1 + bp2[lane + 32] + acc1;
    __syncwarp();

    float f0 = bfc[lane], f1 = bfc[lane + 32];
#pragma unroll 8
    for (int c = 0; c < CC; c++) {
        float ag = agb[c];
        f0 = fmaf(g_WfcT[c * CC + lane],      ag, f0);
        f1 = fmaf(g_WfcT[c * CC + lane + 32], ag, f1);
    }
    out[(size_t)p * CC + lane]      = rx0 + f0;
    out[(size_t)p * CC + lane + 32] = rx1 + f1;
}

// ---------------- launch ----------------
extern "C" void kernel_launch(void* const* d_in, const int* in_sizes, int n_in,
                              void* d_out, int out_size) {
    const float* x   = (const float*)d_in[0];
    const float* pos = (const float*)d_in[1];
    const float* Wq  = (const float*)d_in[2];
    const float* bq  = (const float*)d_in[3];
    const float* Wk  = (const float*)d_in[4];
    const float* bk  = (const float*)d_in[5];
    const float* Wv  = (const float*)d_in[6];
    const float* bv  = (const float*)d_in[7];
    const float* Wp1 = (const float*)d_in[8];
    const float* bp1 = (const float*)d_in[9];
    const float* Wp2 = (const float*)d_in[10];
    const float* bp2 = (const float*)d_in[11];
    const float* Wfc = (const float*)d_in[12];
    const float* bfc = (const float*)d_in[13];
    float* out = (float*)d_out;

    prep1_kernel<<<16, 256>>>(Wq, bq, Wk, bk, Wv, Wp1, bp1, Wp2, bp2, Wfc);
    prep2_kernel<<<(BB * NN) / 16, 256>>>(x, pos, bv);
    knn_kernel<<<(BB * NN) / 8, 256>>>();
    fused_kernel<<<(BB * NN) / 8, 256>>>(x, bp2, bfc, out);
}

// round 7
// speedup vs baseline: 4.9024x; 1.0819x over previous
#include <cuda_runtime.h>
#include <math.h>

#define BB   4
#define NN   4096
#define CC   64
#define KNN  16
#define NH   4
#define FULL 0xffffffffu
#define NEGINF (-3.402823466e+38f)

// ---------------- device scratch (allocation-free) ----------------
__device__ int    g_idx[BB * NN * KNN];
__device__ float4 g_PP [BB * NN];            // packed pos (x,y,z,|p|^2)
__device__ float  g_V  [BB * NN * CC];       // x @ Wv^T + bv
__device__ float  g_KL [BB * NN * NH];       // head-mean k logits (no bias)
__device__ float  g_QM [BB * NN * NH];       // head-mean q logits (no bias)
__device__ float  g_WvT [CC * CC];
__device__ float  g_WpT [CC * CC];
__device__ float  g_WfcT[CC * CC];
__device__ float  g_Wkm [CC * NH];
__device__ float  g_Wqm [CC * NH];
__device__ float  g_Wpm [CC * NH];
__device__ float  g_PW1 [CC * 4];
__device__ float  g_CB  [NH];

// ---------------- prep1 ----------------
__global__ void prep1_kernel(const float* __restrict__ Wq, const float* __restrict__ bq,
                             const float* __restrict__ Wk, const float* __restrict__ bk,
                             const float* __restrict__ Wv,
                             const float* __restrict__ Wp1, const float* __restrict__ bp1,
                             const float* __restrict__ Wp2, const float* __restrict__ bp2,
                             const float* __restrict__ Wfc) {
    int tg = blockIdx.x * 256 + threadIdx.x;
    {
        int r = tg >> 6, c = tg & 63;
        g_WvT [c * CC + r] = Wv [tg];
        g_WpT [c * CC + r] = Wp2[tg];
        g_WfcT[c * CC + r] = Wfc[tg];
    }
    if (blockIdx.x == 0) {
        int t = threadIdx.x;
        int c = t >> 2, h = t & 3;
        float sk = 0.f, sq = 0.f, sp = 0.f;
#pragma unroll
        for (int d = 0; d < 16; d++) {
            sk += Wk [(h * 16 + d) * CC + c];
            sq += Wq [(h * 16 + d) * CC + c];
            sp += Wp2[(h * 16 + d) * CC + c];
        }
        g_Wkm[c * NH + h] = sk * (1.f / 16.f);
        g_Wqm[c * NH + h] = sq * (1.f / 16.f);
        g_Wpm[c * NH + h] = sp * (1.f / 16.f);
        if (t < CC) {
            g_PW1[t * 4 + 0] = Wp1[t * 3 + 0];
            g_PW1[t * 4 + 1] = Wp1[t * 3 + 1];
            g_PW1[t * 4 + 2] = Wp1[t * 3 + 2];
            g_PW1[t * 4 + 3] = bp1[t];
        }
        if (t < NH) {
            float s1 = 0.f, s2 = 0.f, s3 = 0.f;
            for (int d = 0; d < 16; d++) {
                s1 += bq [t * 16 + d];
                s2 += bk [t * 16 + d];
                s3 += bp2[t * 16 + d];
            }
            g_CB[t] = (s1 - s2 + s3) * (1.f / 16.f);
        }
    }
}

// ---------------- prep2 ----------------
__global__ __launch_bounds__(256) void prep2_kernel(const float* __restrict__ x,
                                                    const float* __restrict__ pos,
                                                    const float* __restrict__ bv) {
    __shared__ float xs[16 * CC];
    const int t = threadIdx.x;
    const int pbase = blockIdx.x * 16;

    ((float4*)xs)[t] = ((const float4*)(x + (size_t)pbase * CC))[t];
    __syncthreads();

    const int pt = t >> 4;
    const int jj = t & 15;
    const int p  = pbase + pt;
    const float* xr = xs + pt * CC;

    float a0 = bv[jj * 4 + 0], a1 = bv[jj * 4 + 1],
          a2 = bv[jj * 4 + 2], a3 = bv[jj * 4 + 3];
#pragma unroll 8
    for (int c = 0; c < CC; c++) {
        float xv = xr[c];
        float4 w = ((const float4*)(g_WvT + c * CC))[jj];
        a0 = fmaf(xv, w.x, a0); a1 = fmaf(xv, w.y, a1);
        a2 = fmaf(xv, w.z, a2); a3 = fmaf(xv, w.w, a3);
    }
    ((float4*)(g_V + (size_t)p * CC))[jj] = make_float4(a0, a1, a2, a3);

    if (jj < 4) {
        float s = 0.f;
#pragma unroll 8
        for (int c = 0; c < CC; c++) s = fmaf(xr[c], g_Wkm[c * 4 + jj], s);
        g_KL[(size_t)p * 4 + jj] = s;
    } else if (jj < 8) {
        int h = jj - 4;
        float s = 0.f;
#pragma unroll 8
        for (int c = 0; c < CC; c++) s = fmaf(xr[c], g_Wqm[c * 4 + h], s);
        g_QM[(size_t)p * 4 + h] = s;
    } else if (jj == 8) {
        float px = pos[(size_t)p * 3 + 0];
        float py = pos[(size_t)p * 3 + 1];
        float pz = pos[(size_t)p * 3 + 2];
        float nn = px * px; nn = fmaf(py, py, nn); nn = fmaf(pz, pz, nn);
        g_PP[p] = make_float4(px, py, pz, nn);
    }
}

// ---------------- kNN helpers ----------------
__device__ __forceinline__ void warp_min16(float tv, int ti,
                                           float& mv, int& mI, int& ml) {
    mv = tv; mI = ti; ml = threadIdx.x & 31;
#pragma unroll
    for (int off = 1; off < 16; off <<= 1) {
        float ov = __shfl_xor_sync(FULL, mv, off);
        int   oi = __shfl_xor_sync(FULL, mI, off);
        int   ol = __shfl_xor_sync(FULL, ml, off);
        if (ov < mv || (ov == mv && oi > mI)) { mv = ov; mI = oi; ml = ol; }
    }
    mv = __shfl_sync(FULL, mv, 0);
    mI = __shfl_sync(FULL, mI, 0);
    ml = __shfl_sync(FULL, ml, 0);
}

__device__ __forceinline__ float knn_dist(const float4 qp, const float4 c4) {
    float inner = qp.x * c4.x;
    inner = fmaf(qp.y, c4.y, inner);
    inner = fmaf(qp.z, c4.z, inner);
    return fmaf(2.0f, inner, (-qp.w) - c4.w);
}

// ---------------- kNN: two-pass threshold, per-lane 5-deep buffer ---------
__global__ __launch_bounds__(256) void knn_kernel() {
    const int wid  = threadIdx.x >> 5;
    const int lane = threadIdx.x & 31;
    const int q    = blockIdx.x * 8 + wid;
    const int b    = q >> 12;
    const float4* PPb = g_PP + (size_t)b * NN;

    const float4 qp = PPb[q & 4095];

    // ---- pass 1: per-lane max (branch-free, 2 chains) ----
    float mx0 = NEGINF, mx1 = NEGINF;
    for (int mi0 = 0; mi0 < NN; mi0 += 64) {
        float da = knn_dist(qp, __ldg(&PPb[mi0 + lane]));
        float db = knn_dist(qp, __ldg(&PPb[mi0 + 32 + lane]));
        mx0 = fmaxf(mx0, da);
        mx1 = fmaxf(mx1, db);
    }
    float mx = fmaxf(mx0, mx1);

    // ---- bitonic ascending sort of 32 lane-maxes; L = rank-16 from top ----
    float sx = mx;
#pragma unroll
    for (int k = 2; k <= 32; k <<= 1) {
#pragma unroll
        for (int j = k >> 1; j > 0; j >>= 1) {
            float y = __shfl_xor_sync(FULL, sx, j);
            bool up      = ((lane & k) == 0);
            bool lower   = ((lane & j) == 0);
            bool wantMax = up ? !lower : lower;
            sx = wantMax ? fmaxf(sx, y) : fminf(sx, y);
        }
    }
    const float L = __shfl_sync(FULL, sx, 16);   // 16th largest (<= t16 provably)

    // ---- pass 2: collect hits (d >= L) into per-lane 5-deep shift buffer ---
    float b0 = NEGINF, b1 = NEGINF, b2 = NEGINF, b3 = NEGINF, b4 = NEGINF;
    int   j0 = 0x40000000 + lane * 8,     j1 = j0 + 1, j2 = j0 + 2,
          j3 = j0 + 3,                    j4 = j0 + 4;
    int cnt = 0;
#pragma unroll 2
    for (int mi0 = 0; mi0 < NN; mi0 += 32) {
        int mi = mi0 + lane;
        float d = knn_dist(qp, __ldg(&PPb[mi]));
        if (d >= L) {
            b4 = b3; j4 = j3; b3 = b2; j3 = j2; b2 = b1; j2 = j1;
            b1 = b0; j1 = j0; b0 = d;  j0 = mi;
            cnt++;
        }
    }

    if (!__ballot_sync(FULL, cnt > 5)) {
        // ---- selection: 16 warp-argmax pops with (value desc, idx asc) ----
#pragma unroll
        for (int s = 0; s < KNN; s++) {
            // lane-best over 5 slots (static, tie -> lower idx)
            float lv = b0; int li = j0;
            if (b1 > lv || (b1 == lv && j1 < li)) { lv = b1; li = j1; }
            if (b2 > lv || (b2 == lv && j2 < li)) { lv = b2; li = j2; }
            if (b3 > lv || (b3 == lv && j3 < li)) { lv = b3; li = j3; }
            if (b4 > lv || (b4 == lv && j4 < li)) { lv = b4; li = j4; }
            // warp argmax
            float bvv = lv; int bii = li;
#pragma unroll
            for (int off = 16; off >= 1; off >>= 1) {
                float ov = __shfl_xor_sync(FULL, bvv, off);
                int   oi = __shfl_xor_sync(FULL, bii, off);
                if (ov > bvv || (ov == bvv && oi < bii)) { bvv = ov; bii = oi; }
            }
            if (lane == 0) g_idx[(size_t)q * KNN + s] = bii;
            // remove winner (idx is unique -> exactly one slot matches)
            bool m0 = (j0 == bii), m1 = (j1 == bii), m2 = (j2 == bii),
                 m3 = (j3 == bii), m4 = (j4 == bii);
            b0 = m0 ? NEGINF : b0;  b1 = m1 ? NEGINF : b1;
            b2 = m2 ? NEGINF : b2;  b3 = m3 ? NEGINF : b3;
            b4 = m4 ? NEGINF : b4;
        }
    } else {
        // ---- rare exact fallback (verified R6 path) ----
        float tv = NEGINF; int ti = 0x7fffffff - lane;
        float wv = NEGINF; int wm = 0x7fffffff;
        for (int mi0 = 0; mi0 < NN; mi0 += 32) {
            int mi = mi0 + lane;
            float d = knn_dist(qp, PPb[mi]);
            bool pred = (d > wv) || (d == wv && mi < wm);
            unsigned mask = __ballot_sync(FULL, pred);
            while (mask) {
                int src = __ffs(mask) - 1; mask &= mask - 1;
                float dc = __shfl_sync(FULL, d, src);
                int   mc = __shfl_sync(FULL, mi, src);
                float mv; int mI, ml;
                warp_min16(tv, ti, mv, mI, ml);
                if (dc > mv || (dc == mv && mc < mI)) {
                    if (lane == ml) { tv = dc; ti = mc; }
                    warp_min16(tv, ti, mv, mI, ml);
                }
                wv = mv; wm = mI;
            }
        }
        if (lane < KNN) g_idx[(size_t)q * KNN + lane] = ti;
    }
}

// ---------------- fused: warp-per-point (unchanged) --------------
#define HSTR 65
__global__ __launch_bounds__(256) void fused_kernel(
    const float* __restrict__ x,  const float* __restrict__ bp2,
    const float* __restrict__ bfc, float* __restrict__ out)
{
    __shared__ float hs   [8 * KNN * HSTR];
    __shared__ float attns[8 * KNN * NH];
    __shared__ float As   [8 * NH * CC];
    __shared__ float aggs [8 * CC];

    const int wid  = threadIdx.x >> 5;
    const int lane = threadIdx.x & 31;
    const int p    = blockIdx.x * 8 + wid;
    const int b    = p >> 12;

    float* hsb = hs    + wid * KNN * HSTR;
    float* atb = attns + wid * KNN * NH;
    float* Ab  = As    + wid * NH * CC;
    float* agb = aggs  + wid * CC;

    const int k    = lane >> 1;
    const int half = lane & 1;

    float rx0 = x[(size_t)p * CC + lane];
    float rx1 = x[(size_t)p * CC + lane + 32];
    float4 qp = g_PP[p];

    int m = 0;
    float4 kl4 = make_float4(0.f, 0.f, 0.f, 0.f);
    float pdx = 0.f, pdy = 0.f, pdz = 0.f;
    if (half == 0) {
        m = g_idx[(size_t)p * KNN + k];
        float4 np = g_PP[(size_t)b * NN + m];
        pdx = qp.x - np.x; pdy = qp.y - np.y; pdz = qp.z - np.z;
        kl4 = ((const float4*)g_KL)[(size_t)b * NN + m];
    }
    int src0 = lane & ~1;
    pdx = __shfl_sync(FULL, pdx, src0);
    pdy = __shfl_sync(FULL, pdy, src0);
    pdz = __shfl_sync(FULL, pdz, src0);

    float4 qm4 = ((const float4*)g_QM)[p];
    float4 cb4 = *(const float4*)g_CB;

    float mp0 = 0.f, mp1 = 0.f, mp2 = 0.f, mp3 = 0.f;
#pragma unroll 8
    for (int i = 0; i < 32; i++) {
        int c = half * 32 + i;
        float4 pw = ((const float4*)g_PW1)[c];
        float hv = fmaf(pw.x, pdx, fmaf(pw.y, pdy, fmaf(pw.z, pdz, pw.w)));
        float rh = fmaxf(hv, 0.f);
        hsb[k * HSTR + c] = rh;
        float4 wm4 = ((const float4*)g_Wpm)[c];
        mp0 = fmaf(rh, wm4.x, mp0); mp1 = fmaf(rh, wm4.y, mp1);
        mp2 = fmaf(rh, wm4.z, mp2); mp3 = fmaf(rh, wm4.w, mp3);
    }
    mp0 += __shfl_xor_sync(FULL, mp0, 1);
    mp1 += __shfl_xor_sync(FULL, mp1, 1);
    mp2 += __shfl_xor_sync(FULL, mp2, 1);
    mp3 += __shfl_xor_sync(FULL, mp3, 1);

    float lg0 = qm4.x + cb4.x - kl4.x + mp0;
    float lg1 = qm4.y + cb4.y - kl4.y + mp1;
    float lg2 = qm4.z + cb4.z - kl4.z + mp2;
    float lg3 = qm4.w + cb4.w - kl4.w + mp3;
    float m0 = lg0, m1 = lg1, m2 = lg2, m3 = lg3;
#pragma unroll
    for (int off = 2; off < 32; off <<= 1) {
        m0 = fmaxf(m0, __shfl_xor_sync(FULL, m0, off));
        m1 = fmaxf(m1, __shfl_xor_sync(FULL, m1, off));
        m2 = fmaxf(m2, __shfl_xor_sync(FULL, m2, off));
        m3 = fmaxf(m3, __shfl_xor_sync(FULL, m3, off));
    }
    float e0 = __expf(lg0 - m0), e1 = __expf(lg1 - m1);
    float e2 = __expf(lg2 - m2), e3 = __expf(lg3 - m3);
    float s0 = e0, s1 = e1, s2 = e2, s3 = e3;
#pragma unroll
    for (int off = 2; off < 32; off <<= 1) {
        s0 += __shfl_xor_sync(FULL, s0, off);
        s1 += __shfl_xor_sync(FULL, s1, off);
        s2 += __shfl_xor_sync(FULL, s2, off);
        s3 += __shfl_xor_sync(FULL, s3, off);
    }
    if (half == 0)
        ((float4*)atb)[k] = make_float4(e0 / s0, e1 / s1, e2 / s2, e3 / s3);
    __syncwarp();

    float A0[4] = {0.f, 0.f, 0.f, 0.f};
    float A1[4] = {0.f, 0.f, 0.f, 0.f};
    float av0 = 0.f, av1 = 0.f;
    bool lo = (lane < 16);
#pragma unroll
    for (int kk = 0; kk < KNN; kk++) {
        float4 a4 = ((const float4*)atb)[kk];
        float hv0 = hsb[kk * HSTR + lane];
        float hv1 = hsb[kk * HSTR + lane + 32];
        A0[0] = fmaf(a4.x, hv0, A0[0]); A0[1] = fmaf(a4.y, hv0, A0[1]);
        A0[2] = fmaf(a4.z, hv0, A0[2]); A0[3] = fmaf(a4.w, hv0, A0[3]);
        A1[0] = fmaf(a4.x, hv1, A1[0]); A1[1] = fmaf(a4.y, hv1, A1[1]);
        A1[2] = fmaf(a4.z, hv1, A1[2]); A1[3] = fmaf(a4.w, hv1, A1[3]);
        int mk = __shfl_sync(FULL, m, kk * 2);
        const float* vr = g_V + ((size_t)b * NN + mk) * CC;
        float aw0 = lo ? a4.x : a4.y;
        float aw1 = lo ? a4.z : a4.w;
        av0 = fmaf(aw0, vr[lane],      av0);
        av1 = fmaf(aw1, vr[lane + 32], av1);
    }
#pragma unroll
    for (int h = 0; h < 4; h++) {
        Ab[h * CC + lane]      = A0[h];
        Ab[h * CC + lane + 32] = A1[h];
    }
    __syncwarp();

    const int h0 = lane >> 4;
    const int h1 = 2 + h0;
    const float* A0r = Ab + h0 * CC;
    const float* A1r = Ab + h1 * CC;
    float acc0 = 0.f, acc1 = 0.f;
#pragma unroll 8
    for (int c = 0; c < CC; c++) {
        float w0 = g_WpT[c * CC + lane];
        float w1 = g_WpT[c * CC + lane + 32];
        acc0 = fmaf(w0, A0r[c], acc0);
        acc1 = fmaf(w1, A1r[c], acc1);
    }
    agb[lane]      = av0 + bp2[lane]      + acc0;
    agb[lane + 32] = av1 + bp2[lane + 32] + acc1;
    __syncwarp();

    float f0 = bfc[lane], f1 = bfc[lane + 32];
#pragma unroll 8
    for (int c = 0; c < CC; c++) {
        float ag = agb[c];
        f0 = fmaf(g_WfcT[c * CC + lane],      ag, f0);
        f1 = fmaf(g_WfcT[c * CC + lane + 32], ag, f1);
    }
    out[(size_t)p * CC + lane]      = rx0 + f0;
    out[(size_t)p * CC + lane + 32] = rx1 + f1;
}

// ---------------- launch ----------------
extern "C" void kernel_launch(void* const* d_in, const int* in_sizes, int n_in,
                              void* d_out, int out_size) {
    const float* x   = (const float*)d_in[0];
    const float* pos = (const float*)d_in[1];
    const float* Wq  = (const float*)d_in[2];
    const float* bq  = (const float*)d_in[3];
    const float* Wk  = (const float*)d_in[4];
    const float* bk  = (const float*)d_in[5];
    const float* Wv  = (const float*)d_in[6];
    const float* bv  = (const float*)d_in[7];
    const float* Wp1 = (const float*)d_in[8];
    const float* bp1 = (const float*)d_in[9];
    const float* Wp2 = (const float*)d_in[10];
    const float* bp2 = (const float*)d_in[11];
    const float* Wfc = (const float*)d_in[12];
    const float* bfc = (const float*)d_in[13];
    float* out = (float*)d_out;

    prep1_kernel<<<16, 256>>>(Wq, bq, Wk, bk, Wv, Wp1, bp1, Wp2, bp2, Wfc);
    prep2_kernel<<<(BB * NN) / 16, 256>>>(x, pos, bv);
    knn_kernel<<<(BB * NN) / 8, 256>>>();
    fused_kernel<<<(BB * NN) / 8, 256>>>(x, bp2, bfc, out);
}

// round 8
// speedup vs baseline: 6.7789x; 1.3828x over previous
#include <cuda_runtime.h>
#include <math.h>

#define BB   4
#define NN   4096
#define CC   64
#define KNN  16
#define NH   4
#define QW   4
#define CAP  64
#define FULL 0xffffffffu
#define NEGINF (-3.402823466e+38f)

// ---------------- device scratch (allocation-free) ----------------
__device__ int    g_idx[BB * NN * KNN];
__device__ float4 g_PP [BB * NN];            // packed pos (x,y,z,|p|^2)
__device__ float  g_V  [BB * NN * CC];       // x @ Wv^T + bv
__device__ float  g_KL [BB * NN * NH];
__device__ float  g_QM [BB * NN * NH];
__device__ float  g_WvT [CC * CC];
__device__ float  g_WpT [CC * CC];
__device__ float  g_WfcT[CC * CC];
__device__ float  g_Wkm [CC * NH];
__device__ float  g_Wqm [CC * NH];
__device__ float  g_Wpm [CC * NH];
__device__ float  g_PW1 [CC * 4];
__device__ float  g_CB  [NH];

// ---------------- prep1 ----------------
__global__ void prep1_kernel(const float* __restrict__ Wq, const float* __restrict__ bq,
                             const float* __restrict__ Wk, const float* __restrict__ bk,
                             const float* __restrict__ Wv,
                             const float* __restrict__ Wp1, const float* __restrict__ bp1,
                             const float* __restrict__ Wp2, const float* __restrict__ bp2,
                             const float* __restrict__ Wfc) {
    int tg = blockIdx.x * 256 + threadIdx.x;
    {
        int r = tg >> 6, c = tg & 63;
        g_WvT [c * CC + r] = Wv [tg];
        g_WpT [c * CC + r] = Wp2[tg];
        g_WfcT[c * CC + r] = Wfc[tg];
    }
    if (blockIdx.x == 0) {
        int t = threadIdx.x;
        int c = t >> 2, h = t & 3;
        float sk = 0.f, sq = 0.f, sp = 0.f;
#pragma unroll
        for (int d = 0; d < 16; d++) {
            sk += Wk [(h * 16 + d) * CC + c];
            sq += Wq [(h * 16 + d) * CC + c];
            sp += Wp2[(h * 16 + d) * CC + c];
        }
        g_Wkm[c * NH + h] = sk * (1.f / 16.f);
        g_Wqm[c * NH + h] = sq * (1.f / 16.f);
        g_Wpm[c * NH + h] = sp * (1.f / 16.f);
        if (t < CC) {
            g_PW1[t * 4 + 0] = Wp1[t * 3 + 0];
            g_PW1[t * 4 + 1] = Wp1[t * 3 + 1];
            g_PW1[t * 4 + 2] = Wp1[t * 3 + 2];
            g_PW1[t * 4 + 3] = bp1[t];
        }
        if (t < NH) {
            float s1 = 0.f, s2 = 0.f, s3 = 0.f;
            for (int d = 0; d < 16; d++) {
                s1 += bq [t * 16 + d];
                s2 += bk [t * 16 + d];
                s3 += bp2[t * 16 + d];
            }
            g_CB[t] = (s1 - s2 + s3) * (1.f / 16.f);
        }
    }
}

// ---------------- prep2 ----------------
__global__ __launch_bounds__(256) void prep2_kernel(const float* __restrict__ x,
                                                    const float* __restrict__ pos,
                                                    const float* __restrict__ bv) {
    __shared__ float xs[16 * CC];
    const int t = threadIdx.x;
    const int pbase = blockIdx.x * 16;

    ((float4*)xs)[t] = ((const float4*)(x + (size_t)pbase * CC))[t];
    __syncthreads();

    const int pt = t >> 4;
    const int jj = t & 15;
    const int p  = pbase + pt;
    const float* xr = xs + pt * CC;

    float a0 = bv[jj * 4 + 0], a1 = bv[jj * 4 + 1],
          a2 = bv[jj * 4 + 2], a3 = bv[jj * 4 + 3];
#pragma unroll 8
    for (int c = 0; c < CC; c++) {
        float xv = xr[c];
        float4 w = ((const float4*)(g_WvT + c * CC))[jj];
        a0 = fmaf(xv, w.x, a0); a1 = fmaf(xv, w.y, a1);
        a2 = fmaf(xv, w.z, a2); a3 = fmaf(xv, w.w, a3);
    }
    ((float4*)(g_V + (size_t)p * CC))[jj] = make_float4(a0, a1, a2, a3);

    if (jj < 4) {
        float s = 0.f;
#pragma unroll 8
        for (int c = 0; c < CC; c++) s = fmaf(xr[c], g_Wkm[c * 4 + jj], s);
        g_KL[(size_t)p * 4 + jj] = s;
    } else if (jj < 8) {
        int h = jj - 4;
        float s = 0.f;
#pragma unroll 8
        for (int c = 0; c < CC; c++) s = fmaf(xr[c], g_Wqm[c * 4 + h], s);
        g_QM[(size_t)p * 4 + h] = s;
    } else if (jj == 8) {
        float px = pos[(size_t)p * 3 + 0];
        float py = pos[(size_t)p * 3 + 1];
        float pz = pos[(size_t)p * 3 + 2];
        float nn = px * px; nn = fmaf(py, py, nn); nn = fmaf(pz, pz, nn);
        g_PP[p] = make_float4(px, py, pz, nn);
    }
}

// ---------------- kNN helpers ----------------
__device__ __forceinline__ void warp_min16(float tv, int ti,
                                           float& mv, int& mI, int& ml) {
    mv = tv; mI = ti; ml = threadIdx.x & 31;
#pragma unroll
    for (int off = 1; off < 16; off <<= 1) {
        float ov = __shfl_xor_sync(FULL, mv, off);
        int   oi = __shfl_xor_sync(FULL, mI, off);
        int   ol = __shfl_xor_sync(FULL, ml, off);
        if (ov < mv || (ov == mv && oi > mI)) { mv = ov; mI = oi; ml = ol; }
    }
    mv = __shfl_sync(FULL, mv, 0);
    mI = __shfl_sync(FULL, mI, 0);
    ml = __shfl_sync(FULL, ml, 0);
}

__device__ __forceinline__ float knn_dist(const float4 qp, const float4 c4) {
    float inner = qp.x * c4.x;
    inner = fmaf(qp.y, c4.y, inner);
    inner = fmaf(qp.z, c4.z, inner);
    return fmaf(2.0f, inner, (-qp.w) - c4.w);
}

// exact fallback for one query (verified R6 path)
__device__ void knn_exact(const float4* PPb, const float4 qp, int q) {
    const int lane = threadIdx.x & 31;
    float tv = NEGINF; int ti = 0x7fffffff - lane;
    float wv = NEGINF; int wm = 0x7fffffff;
    for (int mi0 = 0; mi0 < NN; mi0 += 32) {
        int mi = mi0 + lane;
        float d = knn_dist(qp, PPb[mi]);
        bool pred = (d > wv) || (d == wv && mi < wm);
        unsigned mask = __ballot_sync(FULL, pred);
        while (mask) {
            int src = __ffs(mask) - 1; mask &= mask - 1;
            float dc = __shfl_sync(FULL, d, src);
            int   mc = __shfl_sync(FULL, mi, src);
            float mv; int mI, ml;
            warp_min16(tv, ti, mv, mI, ml);
            if (dc > mv || (dc == mv && mc < mI)) {
                if (lane == ml) { tv = dc; ti = mc; }
                warp_min16(tv, ti, mv, mI, ml);
            }
            wv = mv; wm = mI;
        }
    }
    if (lane < KNN) g_idx[(size_t)q * KNN + lane] = ti;
}

// bitonic ascending sort of one value across 32 lanes; returns lane'th element
__device__ __forceinline__ float warp_rank16(float mx) {
    const int lane = threadIdx.x & 31;
    float sx = mx;
#pragma unroll
    for (int k = 2; k <= 32; k <<= 1) {
#pragma unroll
        for (int j = k >> 1; j > 0; j >>= 1) {
            float y = __shfl_xor_sync(FULL, sx, j);
            bool up      = ((lane & k) == 0);
            bool lower   = ((lane & j) == 0);
            bool wantMax = up ? !lower : lower;
            sx = wantMax ? fmaxf(sx, y) : fminf(sx, y);
        }
    }
    return __shfl_sync(FULL, sx, 16);
}

// ---------------- kNN: 4 queries/warp, threshold + smem hit lists ---------
__global__ __launch_bounds__(256) void knn_kernel() {
    __shared__ float sval[8][QW][CAP];
    __shared__ int   sidx[8][QW][CAP];
    __shared__ int   scnt[8][QW];

    const int wid  = threadIdx.x >> 5;
    const int lane = threadIdx.x & 31;
    const int qbase = (blockIdx.x * 8 + wid) * QW;
    const int b    = qbase >> 12;
    const float4* PPb = g_PP + (size_t)b * NN;
    const int qloc = qbase & 4095;

    const float4 qp0 = __ldg(&PPb[qloc + 0]);
    const float4 qp1 = __ldg(&PPb[qloc + 1]);
    const float4 qp2 = __ldg(&PPb[qloc + 2]);
    const float4 qp3 = __ldg(&PPb[qloc + 3]);

    // ---- pass 1: per-lane max for 4 queries (branch-free, 2 chains) ----
    float ma0 = NEGINF, ma1 = NEGINF, ma2 = NEGINF, ma3 = NEGINF;
    float mb0 = NEGINF, mb1 = NEGINF, mb2 = NEGINF, mb3 = NEGINF;
    for (int mi0 = 0; mi0 < NN; mi0 += 64) {
        float4 ca = __ldg(&PPb[mi0 + lane]);
        float4 cb = __ldg(&PPb[mi0 + 32 + lane]);
        ma0 = fmaxf(ma0, knn_dist(qp0, ca));
        ma1 = fmaxf(ma1, knn_dist(qp1, ca));
        ma2 = fmaxf(ma2, knn_dist(qp2, ca));
        ma3 = fmaxf(ma3, knn_dist(qp3, ca));
        mb0 = fmaxf(mb0, knn_dist(qp0, cb));
        mb1 = fmaxf(mb1, knn_dist(qp1, cb));
        mb2 = fmaxf(mb2, knn_dist(qp2, cb));
        mb3 = fmaxf(mb3, knn_dist(qp3, cb));
    }
    const float L0 = warp_rank16(fmaxf(ma0, mb0));
    const float L1 = warp_rank16(fmaxf(ma1, mb1));
    const float L2 = warp_rank16(fmaxf(ma2, mb2));
    const float L3 = warp_rank16(fmaxf(ma3, mb3));

    // ---- pass 2: emit hits (d >= L) to smem lists ----
    if (lane < QW) scnt[wid][lane] = 0;
    __syncwarp();
#pragma unroll 2
    for (int mi0 = 0; mi0 < NN; mi0 += 32) {
        int mi = mi0 + lane;
        float4 c4 = __ldg(&PPb[mi]);
        float d0 = knn_dist(qp0, c4);
        float d1 = knn_dist(qp1, c4);
        float d2 = knn_dist(qp2, c4);
        float d3 = knn_dist(qp3, c4);
        bool p0 = d0 >= L0, p1 = d1 >= L1, p2 = d2 >= L2, p3 = d3 >= L3;
        if (p0 | p1 | p2 | p3) {
            if (p0) { int s = atomicAdd(&scnt[wid][0], 1);
                      if (s < CAP) { sval[wid][0][s] = d0; sidx[wid][0][s] = mi; } }
            if (p1) { int s = atomicAdd(&scnt[wid][1], 1);
                      if (s < CAP) { sval[wid][1][s] = d1; sidx[wid][1][s] = mi; } }
            if (p2) { int s = atomicAdd(&scnt[wid][2], 1);
                      if (s < CAP) { sval[wid][2][s] = d2; sidx[wid][2][s] = mi; } }
            if (p3) { int s = atomicAdd(&scnt[wid][3], 1);
                      if (s < CAP) { sval[wid][3][s] = d3; sidx[wid][3][s] = mi; } }
        }
    }
    __syncwarp();

    // ---- selection: 16 argmax pops per query over <=64 hits ----
#pragma unroll
    for (int j = 0; j < QW; j++) {
        int cnt = scnt[wid][j];
        if (cnt <= CAP) {
            float v0 = (lane < cnt)      ? sval[wid][j][lane]      : NEGINF;
            int   x0 = (lane < cnt)      ? sidx[wid][j][lane]      : 0x40000000 + lane;
            float v1 = (lane + 32 < cnt) ? sval[wid][j][lane + 32] : NEGINF;
            int   x1 = (lane + 32 < cnt) ? sidx[wid][j][lane + 32] : 0x40000040 + lane;
#pragma unroll
            for (int s = 0; s < KNN; s++) {
                float lv = v0; int li = x0;
                if (v1 > lv || (v1 == lv && x1 < li)) { lv = v1; li = x1; }
                float bvv = lv; int bii = li;
#pragma unroll
                for (int off = 16; off >= 1; off >>= 1) {
                    float ov = __shfl_xor_sync(FULL, bvv, off);
                    int   oi = __shfl_xor_sync(FULL, bii, off);
                    if (ov > bvv || (ov == bvv && oi < bii)) { bvv = ov; bii = oi; }
                }
                if (lane == 0) g_idx[(size_t)(qbase + j) * KNN + s] = bii;
                if (x0 == bii) v0 = NEGINF;
                if (x1 == bii) v1 = NEGINF;
            }
        } else {
            const float4 qpj = (j == 0) ? qp0 : (j == 1) ? qp1 : (j == 2) ? qp2 : qp3;
            knn_exact(PPb, qpj, qbase + j);
        }
    }
}

// ---------------- fused: warp-per-point (unchanged) --------------
#define HSTR 65
__global__ __launch_bounds__(256) void fused_kernel(
    const float* __restrict__ x,  const float* __restrict__ bp2,
    const float* __restrict__ bfc, float* __restrict__ out)
{
    __shared__ float hs   [8 * KNN * HSTR];
    __shared__ float attns[8 * KNN * NH];
    __shared__ float As   [8 * NH * CC];
    __shared__ float aggs [8 * CC];

    const int wid  = threadIdx.x >> 5;
    const int lane = threadIdx.x & 31;
    const int p    = blockIdx.x * 8 + wid;
    const int b    = p >> 12;

    float* hsb = hs    + wid * KNN * HSTR;
    float* atb = attns + wid * KNN * NH;
    float* Ab  = As    + wid * NH * CC;
    float* agb = aggs  + wid * CC;

    const int k    = lane >> 1;
    const int half = lane & 1;

    float rx0 = x[(size_t)p * CC + lane];
    float rx1 = x[(size_t)p * CC + lane + 32];
    float4 qp = g_PP[p];

    int m = 0;
    float4 kl4 = make_float4(0.f, 0.f, 0.f, 0.f);
    float pdx = 0.f, pdy = 0.f, pdz = 0.f;
    if (half == 0) {
        m = g_idx[(size_t)p * KNN + k];
        float4 np = g_PP[(size_t)b * NN + m];
        pdx = qp.x - np.x; pdy = qp.y - np.y; pdz = qp.z - np.z;
        kl4 = ((const float4*)g_KL)[(size_t)b * NN + m];
    }
    int src0 = lane & ~1;
    pdx = __shfl_sync(FULL, pdx, src0);
    pdy = __shfl_sync(FULL, pdy, src0);
    pdz = __shfl_sync(FULL, pdz, src0);

    float4 qm4 = ((const float4*)g_QM)[p];
    float4 cb4 = *(const float4*)g_CB;

    float mp0 = 0.f, mp1 = 0.f, mp2 = 0.f, mp3 = 0.f;
#pragma unroll 8
    for (int i = 0; i < 32; i++) {
        int c = half * 32 + i;
        float4 pw = ((const float4*)g_PW1)[c];
        float hv = fmaf(pw.x, pdx, fmaf(pw.y, pdy, fmaf(pw.z, pdz, pw.w)));
        float rh = fmaxf(hv, 0.f);
        hsb[k * HSTR + c] = rh;
        float4 wm4 = ((const float4*)g_Wpm)[c];
        mp0 = fmaf(rh, wm4.x, mp0); mp1 = fmaf(rh, wm4.y, mp1);
        mp2 = fmaf(rh, wm4.z, mp2); mp3 = fmaf(rh, wm4.w, mp3);
    }
    mp0 += __shfl_xor_sync(FULL, mp0, 1);
    mp1 += __shfl_xor_sync(FULL, mp1, 1);
    mp2 += __shfl_xor_sync(FULL, mp2, 1);
    mp3 += __shfl_xor_sync(FULL, mp3, 1);

    float lg0 = qm4.x + cb4.x - kl4.x + mp0;
    float lg1 = qm4.y + cb4.y - kl4.y + mp1;
    float lg2 = qm4.z + cb4.z - kl4.z + mp2;
    float lg3 = qm4.w + cb4.w - kl4.w + mp3;
    float m0 = lg0, m1 = lg1, m2 = lg2, m3 = lg3;
#pragma unroll
    for (int off = 2; off < 32; off <<= 1) {
        m0 = fmaxf(m0, __shfl_xor_sync(FULL, m0, off));
        m1 = fmaxf(m1, __shfl_xor_sync(FULL, m1, off));
        m2 = fmaxf(m2, __shfl_xor_sync(FULL, m2, off));
        m3 = fmaxf(m3, __shfl_xor_sync(FULL, m3, off));
    }
    float e0 = __expf(lg0 - m0), e1 = __expf(lg1 - m1);
    float e2 = __expf(lg2 - m2), e3 = __expf(lg3 - m3);
    float s0 = e0, s1 = e1, s2 = e2, s3 = e3;
#pragma unroll
    for (int off = 2; off < 32; off <<= 1) {
        s0 += __shfl_xor_sync(FULL, s0, off);
        s1 += __shfl_xor_sync(FULL, s1, off);
        s2 += __shfl_xor_sync(FULL, s2, off);
        s3 += __shfl_xor_sync(FULL, s3, off);
    }
    if (half == 0)
        ((float4*)atb)[k] = make_float4(e0 / s0, e1 / s1, e2 / s2, e3 / s3);
    __syncwarp();

    float A0[4] = {0.f, 0.f, 0.f, 0.f};
    float A1[4] = {0.f, 0.f, 0.f, 0.f};
    float av0 = 0.f, av1 = 0.f;
    bool lo = (lane < 16);
#pragma unroll
    for (int kk = 0; kk < KNN; kk++) {
        float4 a4 = ((const float4*)atb)[kk];
        float hv0 = hsb[kk * HSTR + lane];
        float hv1 = hsb[kk * HSTR + lane + 32];
        A0[0] = fmaf(a4.x, hv0, A0[0]); A0[1] = fmaf(a4.y, hv0, A0[1]);
        A0[2] = fmaf(a4.z, hv0, A0[2]); A0[3] = fmaf(a4.w, hv0, A0[3]);
        A1[0] = fmaf(a4.x, hv1, A1[0]); A1[1] = fmaf(a4.y, hv1, A1[1]);
        A1[2] = fmaf(a4.z, hv1, A1[2]); A1[3] = fmaf(a4.w, hv1, A1[3]);
        int mk = __shfl_sync(FULL, m, kk * 2);
        const float* vr = g_V + ((size_t)b * NN + mk) * CC;
        float aw0 = lo ? a4.x : a4.y;
        float aw1 = lo ? a4.z : a4.w;
        av0 = fmaf(aw0, vr[lane],      av0);
        av1 = fmaf(aw1, vr[lane + 32], av1);
    }
#pragma unroll
    for (int h = 0; h < 4; h++) {
        Ab[h * CC + lane]      = A0[h];
        Ab[h * CC + lane + 32] = A1[h];
    }
    __syncwarp();

    const int h0 = lane >> 4;
    const int h1 = 2 + h0;
    const float* A0r = Ab + h0 * CC;
    const float* A1r = Ab + h1 * CC;
    float acc0 = 0.f, acc1 = 0.f;
#pragma unroll 8
    for (int c = 0; c < CC; c++) {
        float w0 = g_WpT[c * CC + lane];
        float w1 = g_WpT[c * CC + lane + 32];
        acc0 = fmaf(w0, A0r[c], acc0);
        acc1 = fmaf(w1, A1r[c], acc1);
    }
    agb[lane]      = av0 + bp2[lane]      + acc0;
    agb[lane + 32] = av1 + bp2[lane + 32] + acc1;
    __syncwarp();

    float f0 = bfc[lane], f1 = bfc[lane + 32];
#pragma unroll 8
    for (int c = 0; c < CC; c++) {
        float ag = agb[c];
        f0 = fmaf(g_WfcT[c * CC + lane],      ag, f0);
        f1 = fmaf(g_WfcT[c * CC + lane + 32], ag, f1);
    }
    out[(size_t)p * CC + lane]      = rx0 + f0;
    out[(size_t)p * CC + lane + 32] = rx1 + f1;
}

// ---------------- launch ----------------
extern "C" void kernel_launch(void* const* d_in, const int* in_sizes, int n_in,
                              void* d_out, int out_size) {
    const float* x   = (const float*)d_in[0];
    const float* pos = (const float*)d_in[1];
    const float* Wq  = (const float*)d_in[2];
    const float* bq  = (const float*)d_in[3];
    const float* Wk  = (const float*)d_in[4];
    const float* bk  = (const float*)d_in[5];
    const float* Wv  = (const float*)d_in[6];
    const float* bv  = (const float*)d_in[7];
    const float* Wp1 = (const float*)d_in[8];
    const float* bp1 = (const float*)d_in[9];
    const float* Wp2 = (const float*)d_in[10];
    const float* bp2 = (const float*)d_in[11];
    const float* Wfc = (const float*)d_in[12];
    const float* bfc = (const float*)d_in[13];
    float* out = (float*)d_out;

    prep1_kernel<<<16, 256>>>(Wq, bq, Wk, bk, Wv, Wp1, bp1, Wp2, bp2, Wfc);
    prep2_kernel<<<(BB * NN) / 16, 256>>>(x, pos, bv);
    knn_kernel<<<(BB * NN) / (8 * QW), 256>>>();
    fused_kernel<<<(BB * NN) / 8, 256>>>(x, bp2, bfc, out);
}